// round 1
// baseline (speedup 1.0000x reference)
#include <cuda_runtime.h>
#include <math.h>

// Problem constants
#define BATCH   128
#define NPATH   64
#define PLEN    128
#define DIMV    512
#define NSTATE  16
#define DEPTHN  2
#define DINV    1024
#define DTRV    32
#define NCLS    32
#define SEQ     64                 // l = NP
#define ROWSZ   (BATCH*SEQ)        // 8192
#define XZW     (2*DINV)           // 4096
#define HEADK   (NPATH*DIMV)       // 32768
#define HSLABS  64

// ---------------- scratch (static device globals; no allocation) -------------
__device__ float  g_x[(size_t)ROWSZ*DIMV];        // 16 MB  activations [8192,512]
__device__ float  g_xz[(size_t)ROWSZ*XZW];        // 128 MB in_proj out  [8192,4096]
__device__ float  g_uc[(size_t)ROWSZ*DINV];       // 32 MB  conv+silu    [8192,1024]
__device__ float  g_xdbl[(size_t)ROWSZ*64];       // 2 MB   x_proj out   [8192,64]
__device__ float  g_delta[(size_t)ROWSZ*DINV];    // 32 MB  softplus dt  [8192,1024]
__device__ float  g_y[(size_t)ROWSZ*DINV];        // 32 MB  scan out     [8192,1024]
__device__ float2 g_stats[BATCH];                 // final LN mean/rstd
__device__ float  g_hpart[(size_t)HSLABS*BATCH*NCLS]; // head split-K partials

__device__ __forceinline__ float softplusf(float x) {
    return fmaxf(x, 0.0f) + log1pf(expf(-fabsf(x)));
}

// ---------------- stage 1: per-pathway linear + LayerNorm --------------------
// grid (NPATH, BATCH/4), 512 threads. Each block: pathway n, 4 batch rows.
__global__ void __launch_bounds__(512) seg_ln_kernel(
    const float* __restrict__ series, const float* __restrict__ seg_w,
    const float* __restrict__ seg_b,  const float* __restrict__ ln_g,
    const float* __restrict__ ln_b)
{
    const int n  = blockIdx.x;
    const int b0 = blockIdx.y * 4;
    const int d  = threadIdx.x;
    __shared__ float s_s[4][PLEN];
    __shared__ float s_red[512];

    {
        int r = d >> 7, p = d & 127;
        s_s[r][p] = series[(size_t)(b0 + r) * (NPATH*PLEN) + n * PLEN + p];
    }
    __syncthreads();

    float sb = seg_b[n*DIMV + d];
    float acc0 = sb, acc1 = sb, acc2 = sb, acc3 = sb;
    const float* wp = seg_w + (size_t)n * PLEN * DIMV + d;
    #pragma unroll 4
    for (int p = 0; p < PLEN; p++) {
        float w = wp[(size_t)p * DIMV];
        acc0 += s_s[0][p] * w;
        acc1 += s_s[1][p] * w;
        acc2 += s_s[2][p] * w;
        acc3 += s_s[3][p] * w;
    }
    float gam = ln_g[n*DIMV + d], bet = ln_b[n*DIMV + d];
    float accs[4] = {acc0, acc1, acc2, acc3};
    #pragma unroll
    for (int r = 0; r < 4; r++) {
        float v = accs[r];
        s_red[d] = v; __syncthreads();
        for (int s = 256; s > 0; s >>= 1) {
            if (d < s) s_red[d] += s_red[d + s];
            __syncthreads();
        }
        float mu = s_red[0] * (1.0f / DIMV);
        __syncthreads();
        float c = v - mu;
        s_red[d] = c * c; __syncthreads();
        for (int s = 256; s > 0; s >>= 1) {
            if (d < s) s_red[d] += s_red[d + s];
            __syncthreads();
        }
        float var = s_red[0] * (1.0f / DIMV);
        __syncthreads();
        float rstd = rsqrtf(var + 1e-5f);
        g_x[((size_t)(b0 + r) * NPATH + n) * DIMV + d] = c * rstd * gam + bet;
    }
}

// ---------------- generic tiled fp32 GEMM:  C[M,N] = A[M,(lda)] * B[N,K]^T ----
// A row-major with leading dim lda (>= K used), B row-major [N,K].
// EPI: 0 = plain store, 1 = softplus(v + bias[n]).
template<int BM, int BN, int TM, int TN, int EPI>
__global__ void __launch_bounds__(256) gemm_nt(
    const float* __restrict__ A, const float* __restrict__ Bw,
    const float* __restrict__ bias, float* __restrict__ C,
    int M, int N, int K, int lda)
{
    constexpr int BK = 16;
    __shared__ float As[BK][BM];
    __shared__ float Bs[BK][BN];
    const int tid = threadIdx.x;
    const int m0 = blockIdx.y * BM;
    const int n0 = blockIdx.x * BN;
    constexpr int NTX = BN / TN;
    static_assert((BM / TM) * (BN / TN) == 256, "thread tiling");
    const int tx = tid % NTX;
    const int ty = tid / NTX;

    float acc[TM][TN];
    #pragma unroll
    for (int i = 0; i < TM; i++)
        #pragma unroll
        for (int j = 0; j < TN; j++) acc[i][j] = 0.f;

    constexpr int A_F4 = BM * 4;   // BM rows x 16 k = BM*4 float4
    constexpr int B_F4 = BN * 4;

    for (int k0 = 0; k0 < K; k0 += BK) {
        #pragma unroll
        for (int l = 0; l < (A_F4 + 255) / 256; l++) {
            int idx = tid + l * 256;
            if ((A_F4 % 256) == 0 || idx < A_F4) {
                int row = idx >> 2, kq = (idx & 3) << 2;
                float4 v = *(const float4*)(A + (size_t)(m0 + row) * lda + k0 + kq);
                As[kq + 0][row] = v.x; As[kq + 1][row] = v.y;
                As[kq + 2][row] = v.z; As[kq + 3][row] = v.w;
            }
        }
        #pragma unroll
        for (int l = 0; l < (B_F4 + 255) / 256; l++) {
            int idx = tid + l * 256;
            if ((B_F4 % 256) == 0 || idx < B_F4) {
                int row = idx >> 2, kq = (idx & 3) << 2;
                float4 v = *(const float4*)(Bw + (size_t)(n0 + row) * K + k0 + kq);
                Bs[kq + 0][row] = v.x; Bs[kq + 1][row] = v.y;
                Bs[kq + 2][row] = v.z; Bs[kq + 3][row] = v.w;
            }
        }
        __syncthreads();
        #pragma unroll
        for (int kk = 0; kk < BK; kk++) {
            float a[TM], bfr[TN];
            #pragma unroll
            for (int i = 0; i < TM; i++) a[i] = As[kk][ty * TM + i];
            #pragma unroll
            for (int j = 0; j < TN; j++) bfr[j] = Bs[kk][tx * TN + j];
            #pragma unroll
            for (int i = 0; i < TM; i++)
                #pragma unroll
                for (int j = 0; j < TN; j++) acc[i][j] += a[i] * bfr[j];
        }
        __syncthreads();
    }

    #pragma unroll
    for (int i = 0; i < TM; i++) {
        int m = m0 + ty * TM + i;
        #pragma unroll
        for (int j = 0; j < TN; j++) {
            int n = n0 + tx * TN + j;
            float v = acc[i][j];
            if (EPI == 1) v = softplusf(v + bias[n]);
            C[(size_t)m * N + n] = v;
        }
    }
}

// ---------------- causal depthwise conv (k=4) + bias + silu ------------------
// reads u = g_xz[:, 0:DIN], writes g_uc. One thread = 4 channels of one (b,t).
__global__ void __launch_bounds__(256) conv_silu_kernel(
    const float* __restrict__ cw, const float* __restrict__ cb)
{
    int idx = blockIdx.x * blockDim.x + threadIdx.x;   // ROWSZ * DINV/4
    int c4  = (idx & (DINV/4 - 1)) << 2;
    int row = idx >> 8;                                // DINV/4 = 256
    int t   = row & (SEQ - 1);
    const float* urow = g_xz + (size_t)row * XZW + c4;

    float4 w0 = *(const float4*)(cw + (size_t)(c4 + 0) * 4);
    float4 w1 = *(const float4*)(cw + (size_t)(c4 + 1) * 4);
    float4 w2 = *(const float4*)(cw + (size_t)(c4 + 2) * 4);
    float4 w3 = *(const float4*)(cw + (size_t)(c4 + 3) * 4);
    float4 a  = *(const float4*)(cb + c4);

    if (t - 3 >= 0) {
        float4 u = *(const float4*)(urow - (size_t)3 * XZW);
        a.x += u.x * w0.x; a.y += u.y * w1.x; a.z += u.z * w2.x; a.w += u.w * w3.x;
    }
    if (t - 2 >= 0) {
        float4 u = *(const float4*)(urow - (size_t)2 * XZW);
        a.x += u.x * w0.y; a.y += u.y * w1.y; a.z += u.z * w2.y; a.w += u.w * w3.y;
    }
    if (t - 1 >= 0) {
        float4 u = *(const float4*)(urow - (size_t)1 * XZW);
        a.x += u.x * w0.z; a.y += u.y * w1.z; a.z += u.z * w2.z; a.w += u.w * w3.z;
    }
    {
        float4 u = *(const float4*)(urow);
        a.x += u.x * w0.w; a.y += u.y * w1.w; a.z += u.z * w2.w; a.w += u.w * w3.w;
    }
    a.x = a.x / (1.0f + __expf(-a.x));
    a.y = a.y / (1.0f + __expf(-a.y));
    a.z = a.z / (1.0f + __expf(-a.z));
    a.w = a.w / (1.0f + __expf(-a.w));
    *(float4*)(g_uc + (size_t)row * DINV + c4) = a;
}

// ---------------- selective scan + gating epilogue ----------------------------
// grid (BATCH, DINV/256), 256 threads. One thread owns one (b, channel d),
// keeps h[16] in registers, marches t = 0..63.
__global__ void __launch_bounds__(256) scan_kernel(
    const float* __restrict__ A_log, const float* __restrict__ Dp_)
{
    const int b = blockIdx.x;
    const int d = blockIdx.y * 256 + threadIdx.x;
    __shared__ float sB[SEQ][NSTATE];
    __shared__ float sC[SEQ][NSTATE];

    for (int i = threadIdx.x; i < SEQ * 2 * NSTATE; i += 256) {
        int t = i >> 5, j = i & 31;
        float v = g_xdbl[((size_t)(b * SEQ + t)) * 64 + 32 + j];
        if (j < 16) sB[t][j] = v; else sC[t][j - 16] = v;
    }
    __syncthreads();

    float rA[NSTATE];
    #pragma unroll
    for (int n = 0; n < NSTATE; n++) rA[n] = -expf(A_log[(size_t)d * NSTATE + n]);
    const float Dv = Dp_[d];
    float h[NSTATE];
    #pragma unroll
    for (int n = 0; n < NSTATE; n++) h[n] = 0.f;

    const size_t rowbase = (size_t)b * SEQ;
    for (int t = 0; t < SEQ; t++) {
        const size_t row = rowbase + t;
        float delta = g_delta[row * DINV + d];
        float u     = g_uc[row * DINV + d];
        float du    = delta * u;
        float y = 0.f;
        #pragma unroll
        for (int n = 0; n < NSTATE; n++) {
            float dA = __expf(delta * rA[n]);
            h[n] = dA * h[n] + du * sB[t][n];
            y += h[n] * sC[t][n];
        }
        float z = g_xz[row * XZW + DINV + d];
        float silu_z = z / (1.0f + __expf(-z));
        g_y[row * DINV + d] = (y + u * Dv) * silu_z;
    }
}

// ---------------- final LayerNorm stats (per batch row of 32768) -------------
__global__ void __launch_bounds__(256) ln_stats_kernel()
{
    const int b = blockIdx.x;
    const float4* xp = (const float4*)(g_x + (size_t)b * HEADK);
    float s = 0.f, sq = 0.f;
    for (int i = threadIdx.x; i < HEADK / 4; i += 256) {
        float4 v = xp[i];
        s  += v.x + v.y + v.z + v.w;
        sq += v.x*v.x + v.y*v.y + v.z*v.z + v.w*v.w;
    }
    __shared__ float rs[256], rq[256];
    rs[threadIdx.x] = s; rq[threadIdx.x] = sq; __syncthreads();
    for (int st = 128; st > 0; st >>= 1) {
        if (threadIdx.x < st) { rs[threadIdx.x] += rs[threadIdx.x + st];
                                rq[threadIdx.x] += rq[threadIdx.x + st]; }
        __syncthreads();
    }
    if (threadIdx.x == 0) {
        float mu  = rs[0] / (float)HEADK;
        float var = rq[0] / (float)HEADK - mu * mu;
        g_stats[b] = make_float2(mu, rsqrtf(var + 1e-5f));
    }
}

// ---------------- head: split-K GEMM (LN fused on A load) --------------------
// grid = HSLABS blocks, each handles a 512-wide K slab for all 128x32 outputs.
__global__ void __launch_bounds__(256) head_gemm_kernel(
    const float* __restrict__ lng, const float* __restrict__ lnb,
    const float* __restrict__ hw)
{
    constexpr int BK = 16;
    const int slab = blockIdx.x;
    const int kbeg = slab * (HEADK / HSLABS);   // 512
    __shared__ float sX[BK][BATCH];
    __shared__ float sW[BK][NCLS];
    const int tid = threadIdx.x;
    const int tx = tid & 15;    // 2 classes each
    const int ty = tid >> 4;    // 8 batch rows each

    float acc[8][2];
    #pragma unroll
    for (int i = 0; i < 8; i++) { acc[i][0] = 0.f; acc[i][1] = 0.f; }

    for (int k0 = kbeg; k0 < kbeg + HEADK / HSLABS; k0 += BK) {
        #pragma unroll
        for (int l = 0; l < 2; l++) {
            int idx = tid + l * 256;
            int row = idx >> 2, kq = (idx & 3) << 2;
            float2 st = g_stats[row];
            float4 v  = *(const float4*)(g_x + (size_t)row * HEADK + k0 + kq);
            float4 gg = *(const float4*)(lng + k0 + kq);
            float4 bb = *(const float4*)(lnb + k0 + kq);
            sX[kq + 0][row] = (v.x - st.x) * st.y * gg.x + bb.x;
            sX[kq + 1][row] = (v.y - st.x) * st.y * gg.y + bb.y;
            sX[kq + 2][row] = (v.z - st.x) * st.y * gg.z + bb.z;
            sX[kq + 3][row] = (v.w - st.x) * st.y * gg.w + bb.w;
        }
        if (tid < 128) {
            int row = tid >> 2, kq = (tid & 3) << 2;
            float4 v = *(const float4*)(hw + (size_t)row * HEADK + k0 + kq);
            sW[kq + 0][row] = v.x; sW[kq + 1][row] = v.y;
            sW[kq + 2][row] = v.z; sW[kq + 3][row] = v.w;
        }
        __syncthreads();
        #pragma unroll
        for (int kk = 0; kk < BK; kk++) {
            float w0 = sW[kk][tx * 2], w1 = sW[kk][tx * 2 + 1];
            #pragma unroll
            for (int i = 0; i < 8; i++) {
                float a = sX[kk][ty * 8 + i];
                acc[i][0] += a * w0;
                acc[i][1] += a * w1;
            }
        }
        __syncthreads();
    }
    #pragma unroll
    for (int i = 0; i < 8; i++) {
        int m = ty * 8 + i;
        g_hpart[((size_t)slab * BATCH + m) * NCLS + tx * 2 + 0] = acc[i][0];
        g_hpart[((size_t)slab * BATCH + m) * NCLS + tx * 2 + 1] = acc[i][1];
    }
}

__global__ void __launch_bounds__(256) head_reduce_kernel(
    const float* __restrict__ head_b, float* __restrict__ out)
{
    int idx = blockIdx.x * blockDim.x + threadIdx.x;
    if (idx < BATCH * NCLS) {
        float s = head_b[idx & (NCLS - 1)];
        for (int sl = 0; sl < HSLABS; sl++)
            s += g_hpart[(size_t)sl * BATCH * NCLS + idx];
        out[idx] = s;
    }
}

// ---------------- host orchestration -----------------------------------------
extern "C" void kernel_launch(void* const* d_in, const int* in_sizes, int n_in,
                              void* d_out, int out_size)
{
    const float* series    = (const float*)d_in[0];
    const float* seg_w     = (const float*)d_in[1];
    const float* seg_b     = (const float*)d_in[2];
    const float* ln_g      = (const float*)d_in[3];
    const float* ln_b      = (const float*)d_in[4];
    const float* in_proj_w = (const float*)d_in[5];
    const float* conv_w    = (const float*)d_in[6];
    const float* conv_b    = (const float*)d_in[7];
    const float* x_proj_w  = (const float*)d_in[8];
    const float* dt_proj_w = (const float*)d_in[9];
    const float* dt_proj_b = (const float*)d_in[10];
    const float* A_log     = (const float*)d_in[11];
    const float* Dw        = (const float*)d_in[12];
    const float* out_proj_w= (const float*)d_in[13];
    const float* hlng      = (const float*)d_in[14];
    const float* hlnb      = (const float*)d_in[15];
    const float* head_w    = (const float*)d_in[16];
    const float* head_b    = (const float*)d_in[17];
    float* out = (float*)d_out;

    float *px, *pxz, *puc, *pxdbl, *pdelta, *py;
    cudaGetSymbolAddress((void**)&px,     g_x);
    cudaGetSymbolAddress((void**)&pxz,    g_xz);
    cudaGetSymbolAddress((void**)&puc,    g_uc);
    cudaGetSymbolAddress((void**)&pxdbl,  g_xdbl);
    cudaGetSymbolAddress((void**)&pdelta, g_delta);
    cudaGetSymbolAddress((void**)&py,     g_y);

    // 1) segment linear + per-pathway LN -> g_x [8192, 512]
    seg_ln_kernel<<<dim3(NPATH, BATCH/4), 512>>>(series, seg_w, seg_b, ln_g, ln_b);

    for (int dep = 0; dep < DEPTHN; dep++) {
        // 2) in_proj: [8192,512] x [4096,512]^T -> g_xz [8192,4096]
        gemm_nt<128,64,8,4,0><<<dim3(XZW/64, ROWSZ/128), 256>>>(
            px, in_proj_w + (size_t)dep * XZW * DIMV, nullptr, pxz,
            ROWSZ, XZW, DIMV, DIMV);
        // 3) conv + silu -> g_uc [8192,1024]
        conv_silu_kernel<<<(ROWSZ * (DINV/4)) / 256, 256>>>(
            conv_w + (size_t)dep * DINV * 4, conv_b + (size_t)dep * DINV);
        // 4) x_proj: [8192,1024] x [64,1024]^T -> g_xdbl [8192,64]
        gemm_nt<64,64,4,4,0><<<dim3(1, ROWSZ/64), 256>>>(
            puc, x_proj_w + (size_t)dep * 64 * DINV, nullptr, pxdbl,
            ROWSZ, 64, DINV, DINV);
        // 5) dt_proj + bias + softplus: [8192,32 of 64] x [1024,32]^T -> g_delta
        gemm_nt<128,64,8,4,1><<<dim3(DINV/64, ROWSZ/128), 256>>>(
            pxdbl, dt_proj_w + (size_t)dep * DINV * DTRV,
            dt_proj_b + (size_t)dep * DINV, pdelta,
            ROWSZ, DINV, DTRV, 64);
        // 6) selective scan + D skip + silu(z) gate -> g_y [8192,1024]
        scan_kernel<<<dim3(BATCH, DINV/256), 256>>>(
            A_log + (size_t)dep * DINV * NSTATE, Dw + (size_t)dep * DINV);
        // 7) out_proj: [8192,1024] x [512,1024]^T -> g_x [8192,512]
        gemm_nt<128,64,8,4,0><<<dim3(DIMV/64, ROWSZ/128), 256>>>(
            py, out_proj_w + (size_t)dep * DIMV * DINV, nullptr, px,
            ROWSZ, DIMV, DINV, DINV);
    }

    // 8) final LN stats + head GEMM (split-K) + deterministic reduce
    ln_stats_kernel<<<BATCH, 256>>>();
    head_gemm_kernel<<<HSLABS, 256>>>(hlng, hlnb, head_w);
    head_reduce_kernel<<<(BATCH*NCLS + 255)/256, 256>>>(head_b, out);
}

// round 3
// speedup vs baseline: 1.5370x; 1.5370x over previous
#include <cuda_runtime.h>
#include <cuda_bf16.h>
#include <math.h>
#include <stdint.h>

// Problem constants
#define BATCH   128
#define NPATH   64
#define PLEN    128
#define DIMV    512
#define NSTATE  16
#define DEPTHN  2
#define DINV    1024
#define DTRV    32
#define NCLS    32
#define SEQ     64
#define ROWSZ   (BATCH*SEQ)        // 8192
#define XZW     (2*DINV)           // 4096
#define HEADK   (NPATH*DIMV)       // 32768
#define HSLABS  64

// ---------------- scratch (static device globals; no allocation) -------------
__device__ float  g_x[(size_t)ROWSZ*DIMV];
__device__ float  g_xz[(size_t)ROWSZ*XZW];
__device__ float  g_uc[(size_t)ROWSZ*DINV];
__device__ float  g_xdbl[(size_t)ROWSZ*64];
__device__ float  g_delta[(size_t)ROWSZ*DINV];
__device__ float  g_y[(size_t)ROWSZ*DINV];
__device__ float2 g_stats[BATCH];
__device__ float  g_hpart[(size_t)HSLABS*BATCH*NCLS];

__device__ __forceinline__ float softplusf(float x) {
    return fmaxf(x, 0.0f) + log1pf(expf(-fabsf(x)));
}

// split fp32 -> (hi, lo) bf16 pairs, packed 2x16b per u32
__device__ __forceinline__ void cvt_hl(float4 v, uint2& hw, uint2& lw) {
    float f[4] = {v.x, v.y, v.z, v.w};
    unsigned short h[4], l[4];
    #pragma unroll
    for (int i = 0; i < 4; i++) {
        __nv_bfloat16 hb = __float2bfloat16_rn(f[i]);
        h[i] = __bfloat16_as_ushort(hb);
        float r = f[i] - __bfloat162float(hb);
        l[i] = __bfloat16_as_ushort(__float2bfloat16_rn(r));
    }
    hw.x = (uint32_t)h[0] | ((uint32_t)h[1] << 16);
    hw.y = (uint32_t)h[2] | ((uint32_t)h[3] << 16);
    lw.x = (uint32_t)l[0] | ((uint32_t)l[1] << 16);
    lw.y = (uint32_t)l[2] | ((uint32_t)l[3] << 16);
}

__device__ __forceinline__ void mma16816(float* c, const uint32_t* a, const uint32_t* b) {
    asm volatile(
        "mma.sync.aligned.m16n8k16.row.col.f32.bf16.bf16.f32 "
        "{%0,%1,%2,%3}, {%4,%5,%6,%7}, {%8,%9}, {%0,%1,%2,%3};"
        : "+f"(c[0]), "+f"(c[1]), "+f"(c[2]), "+f"(c[3])
        : "r"(a[0]), "r"(a[1]), "r"(a[2]), "r"(a[3]), "r"(b[0]), "r"(b[1]));
}

// =============== HMMA bf16x3 GEMM: C[M,N] = A[M,K] * W[N,K]^T ===============
// Block tile 128 x BN, BK=32 fp32 k per chunk. fp32->bf16 hi/lo split on the
// fly; 3 passes (AhWh + AhWl + AlWh) accumulate in fp32. 8 warps, WM x WN grid.
template<int BN, int WM, int WN>
__global__ void __launch_bounds__(256) hmma_gemm(
    const float* __restrict__ A, const float* __restrict__ W,
    float* __restrict__ C, int M, int N, int K, int lda, int ldb)
{
    constexpr int BM = 128, BK = 32, SA = BK + 4;   // padded stride (72B rows)
    constexpr int WTM = BM / WM, WTN = BN / WN;
    constexpr int MF = WTM / 16, NF = WTN / 8;
    static_assert(WM * WN == 8, "8 warps");
    __shared__ __nv_bfloat16 sAh[BM*SA], sAl[BM*SA];
    __shared__ __nv_bfloat16 sWh[BN*SA], sWl[BN*SA];

    const int tid = threadIdx.x, lane = tid & 31, wid = tid >> 5;
    const int warpM = wid % WM, warpN = wid / WM;
    const int m0 = blockIdx.y * BM, n0 = blockIdx.x * BN;
    const int g = lane >> 2, c2 = (lane & 3) * 2;
    const int mbase = warpM * WTM, nbase = warpN * WTN;

    float acc[MF][NF][4];
    #pragma unroll
    for (int mi = 0; mi < MF; mi++)
        #pragma unroll
        for (int ni = 0; ni < NF; ni++)
            #pragma unroll
            for (int q = 0; q < 4; q++) acc[mi][ni][q] = 0.f;

    for (int kc = 0; kc < K; kc += BK) {
        // ---- load + split A tile: 128 x 32 fp32 ----
        #pragma unroll
        for (int it = 0; it < BM * 8 / 256; it++) {
            int i = tid + it * 256;
            int r = i >> 3, kq = (i & 7) << 2;
            float4 v = *(const float4*)(A + (size_t)(m0 + r) * lda + kc + kq);
            uint2 hw, lw; cvt_hl(v, hw, lw);
            *(uint2*)&sAh[r * SA + kq] = hw;
            *(uint2*)&sAl[r * SA + kq] = lw;
        }
        // ---- load + split W tile: BN x 32 fp32 ----
        #pragma unroll
        for (int it = 0; it < BN * 8 / 256; it++) {
            int i = tid + it * 256;
            int r = i >> 3, kq = (i & 7) << 2;
            float4 v = *(const float4*)(W + (size_t)(n0 + r) * ldb + kc + kq);
            uint2 hw, lw; cvt_hl(v, hw, lw);
            *(uint2*)&sWh[r * SA + kq] = hw;
            *(uint2*)&sWl[r * SA + kq] = lw;
        }
        __syncthreads();

        #pragma unroll
        for (int ks = 0; ks < BK; ks += 16) {
            uint32_t ah[MF][4], al[MF][4], bh[NF][2], bl[NF][2];
            #pragma unroll
            for (int mi = 0; mi < MF; mi++) {
                int r0 = (mbase + mi * 16 + g) * SA + ks + c2;
                int r8 = r0 + 8 * SA;
                ah[mi][0] = *(const uint32_t*)&sAh[r0];
                ah[mi][1] = *(const uint32_t*)&sAh[r8];
                ah[mi][2] = *(const uint32_t*)&sAh[r0 + 8];
                ah[mi][3] = *(const uint32_t*)&sAh[r8 + 8];
            }
            #pragma unroll
            for (int ni = 0; ni < NF; ni++) {
                int rn = (nbase + ni * 8 + g) * SA + ks + c2;
                bh[ni][0] = *(const uint32_t*)&sWh[rn];
                bh[ni][1] = *(const uint32_t*)&sWh[rn + 8];
            }
            // pass 1: Ah * Wh
            #pragma unroll
            for (int mi = 0; mi < MF; mi++)
                #pragma unroll
                for (int ni = 0; ni < NF; ni++)
                    mma16816(acc[mi][ni], ah[mi], bh[ni]);
            // pass 2: Ah * Wl
            #pragma unroll
            for (int ni = 0; ni < NF; ni++) {
                int rn = (nbase + ni * 8 + g) * SA + ks + c2;
                bl[ni][0] = *(const uint32_t*)&sWl[rn];
                bl[ni][1] = *(const uint32_t*)&sWl[rn + 8];
            }
            #pragma unroll
            for (int mi = 0; mi < MF; mi++)
                #pragma unroll
                for (int ni = 0; ni < NF; ni++)
                    mma16816(acc[mi][ni], ah[mi], bl[ni]);
            // pass 3: Al * Wh
            #pragma unroll
            for (int mi = 0; mi < MF; mi++) {
                int r0 = (mbase + mi * 16 + g) * SA + ks + c2;
                int r8 = r0 + 8 * SA;
                al[mi][0] = *(const uint32_t*)&sAl[r0];
                al[mi][1] = *(const uint32_t*)&sAl[r8];
                al[mi][2] = *(const uint32_t*)&sAl[r0 + 8];
                al[mi][3] = *(const uint32_t*)&sAl[r8 + 8];
            }
            #pragma unroll
            for (int mi = 0; mi < MF; mi++)
                #pragma unroll
                for (int ni = 0; ni < NF; ni++)
                    mma16816(acc[mi][ni], al[mi], bh[ni]);
        }
        __syncthreads();
    }

    // ---- epilogue ----
    #pragma unroll
    for (int mi = 0; mi < MF; mi++) {
        int row = m0 + mbase + mi * 16 + g;
        #pragma unroll
        for (int ni = 0; ni < NF; ni++) {
            int col = n0 + nbase + ni * 8 + c2;
            *(float2*)(C + (size_t)row * N + col)
                = make_float2(acc[mi][ni][0], acc[mi][ni][1]);
            *(float2*)(C + (size_t)(row + 8) * N + col)
                = make_float2(acc[mi][ni][2], acc[mi][ni][3]);
        }
    }
}

// ---------------- stage 1: per-pathway linear + LayerNorm --------------------
__global__ void __launch_bounds__(512) seg_ln_kernel(
    const float* __restrict__ series, const float* __restrict__ seg_w,
    const float* __restrict__ seg_b,  const float* __restrict__ ln_g,
    const float* __restrict__ ln_b)
{
    const int n  = blockIdx.x;
    const int b0 = blockIdx.y * 4;
    const int d  = threadIdx.x;
    __shared__ float s_s[4][PLEN];
    __shared__ float s_red[512];

    {
        int r = d >> 7, p = d & 127;
        s_s[r][p] = series[(size_t)(b0 + r) * (NPATH*PLEN) + n * PLEN + p];
    }
    __syncthreads();

    float sb = seg_b[n*DIMV + d];
    float acc0 = sb, acc1 = sb, acc2 = sb, acc3 = sb;
    const float* wp = seg_w + (size_t)n * PLEN * DIMV + d;
    #pragma unroll 4
    for (int p = 0; p < PLEN; p++) {
        float w = wp[(size_t)p * DIMV];
        acc0 += s_s[0][p] * w;
        acc1 += s_s[1][p] * w;
        acc2 += s_s[2][p] * w;
        acc3 += s_s[3][p] * w;
    }
    float gam = ln_g[n*DIMV + d], bet = ln_b[n*DIMV + d];
    float accs[4] = {acc0, acc1, acc2, acc3};
    #pragma unroll
    for (int r = 0; r < 4; r++) {
        float v = accs[r];
        s_red[d] = v; __syncthreads();
        for (int s = 256; s > 0; s >>= 1) {
            if (d < s) s_red[d] += s_red[d + s];
            __syncthreads();
        }
        float mu = s_red[0] * (1.0f / DIMV);
        __syncthreads();
        float c = v - mu;
        s_red[d] = c * c; __syncthreads();
        for (int s = 256; s > 0; s >>= 1) {
            if (d < s) s_red[d] += s_red[d + s];
            __syncthreads();
        }
        float var = s_red[0] * (1.0f / DIMV);
        __syncthreads();
        float rstd = rsqrtf(var + 1e-5f);
        g_x[((size_t)(b0 + r) * NPATH + n) * DIMV + d] = c * rstd * gam + bet;
    }
}

// ---------------- FFMA GEMM (kept for the tiny dt_proj) ----------------------
template<int BM, int BN, int TM, int TN, int EPI>
__global__ void __launch_bounds__(256) gemm_nt(
    const float* __restrict__ A, const float* __restrict__ Bw,
    const float* __restrict__ bias, float* __restrict__ C,
    int M, int N, int K, int lda)
{
    constexpr int BK = 16;
    __shared__ float As[BK][BM];
    __shared__ float Bs[BK][BN];
    const int tid = threadIdx.x;
    const int m0 = blockIdx.y * BM;
    const int n0 = blockIdx.x * BN;
    constexpr int NTX = BN / TN;
    static_assert((BM / TM) * (BN / TN) == 256, "thread tiling");
    const int tx = tid % NTX;
    const int ty = tid / NTX;

    float acc[TM][TN];
    #pragma unroll
    for (int i = 0; i < TM; i++)
        #pragma unroll
        for (int j = 0; j < TN; j++) acc[i][j] = 0.f;

    constexpr int A_F4 = BM * 4;
    constexpr int B_F4 = BN * 4;

    for (int k0 = 0; k0 < K; k0 += BK) {
        #pragma unroll
        for (int l = 0; l < (A_F4 + 255) / 256; l++) {
            int idx = tid + l * 256;
            if ((A_F4 % 256) == 0 || idx < A_F4) {
                int row = idx >> 2, kq = (idx & 3) << 2;
                float4 v = *(const float4*)(A + (size_t)(m0 + row) * lda + k0 + kq);
                As[kq + 0][row] = v.x; As[kq + 1][row] = v.y;
                As[kq + 2][row] = v.z; As[kq + 3][row] = v.w;
            }
        }
        #pragma unroll
        for (int l = 0; l < (B_F4 + 255) / 256; l++) {
            int idx = tid + l * 256;
            if ((B_F4 % 256) == 0 || idx < B_F4) {
                int row = idx >> 2, kq = (idx & 3) << 2;
                float4 v = *(const float4*)(Bw + (size_t)(n0 + row) * K + k0 + kq);
                Bs[kq + 0][row] = v.x; Bs[kq + 1][row] = v.y;
                Bs[kq + 2][row] = v.z; Bs[kq + 3][row] = v.w;
            }
        }
        __syncthreads();
        #pragma unroll
        for (int kk = 0; kk < BK; kk++) {
            float a[TM], bfr[TN];
            #pragma unroll
            for (int i = 0; i < TM; i++) a[i] = As[kk][ty * TM + i];
            #pragma unroll
            for (int j = 0; j < TN; j++) bfr[j] = Bs[kk][tx * TN + j];
            #pragma unroll
            for (int i = 0; i < TM; i++)
                #pragma unroll
                for (int j = 0; j < TN; j++) acc[i][j] += a[i] * bfr[j];
        }
        __syncthreads();
    }

    #pragma unroll
    for (int i = 0; i < TM; i++) {
        int m = m0 + ty * TM + i;
        #pragma unroll
        for (int j = 0; j < TN; j++) {
            int n = n0 + tx * TN + j;
            float v = acc[i][j];
            if (EPI == 1) v = softplusf(v + bias[n]);
            C[(size_t)m * N + n] = v;
        }
    }
}

// ---------------- causal depthwise conv (k=4) + bias + silu ------------------
__global__ void __launch_bounds__(256) conv_silu_kernel(
    const float* __restrict__ cw, const float* __restrict__ cb)
{
    int idx = blockIdx.x * blockDim.x + threadIdx.x;
    int c4  = (idx & (DINV/4 - 1)) << 2;
    int row = idx >> 8;
    int t   = row & (SEQ - 1);
    const float* urow = g_xz + (size_t)row * XZW + c4;

    float4 w0 = *(const float4*)(cw + (size_t)(c4 + 0) * 4);
    float4 w1 = *(const float4*)(cw + (size_t)(c4 + 1) * 4);
    float4 w2 = *(const float4*)(cw + (size_t)(c4 + 2) * 4);
    float4 w3 = *(const float4*)(cw + (size_t)(c4 + 3) * 4);
    float4 a  = *(const float4*)(cb + c4);

    if (t - 3 >= 0) {
        float4 u = *(const float4*)(urow - (size_t)3 * XZW);
        a.x += u.x * w0.x; a.y += u.y * w1.x; a.z += u.z * w2.x; a.w += u.w * w3.x;
    }
    if (t - 2 >= 0) {
        float4 u = *(const float4*)(urow - (size_t)2 * XZW);
        a.x += u.x * w0.y; a.y += u.y * w1.y; a.z += u.z * w2.y; a.w += u.w * w3.y;
    }
    if (t - 1 >= 0) {
        float4 u = *(const float4*)(urow - (size_t)1 * XZW);
        a.x += u.x * w0.z; a.y += u.y * w1.z; a.z += u.z * w2.z; a.w += u.w * w3.z;
    }
    {
        float4 u = *(const float4*)(urow);
        a.x += u.x * w0.w; a.y += u.y * w1.w; a.z += u.z * w2.w; a.w += u.w * w3.w;
    }
    a.x = a.x / (1.0f + __expf(-a.x));
    a.y = a.y / (1.0f + __expf(-a.y));
    a.z = a.z / (1.0f + __expf(-a.z));
    a.w = a.w / (1.0f + __expf(-a.w));
    *(float4*)(g_uc + (size_t)row * DINV + c4) = a;
}

// ---------------- selective scan + gating epilogue ----------------------------
__global__ void __launch_bounds__(256) scan_kernel(
    const float* __restrict__ A_log, const float* __restrict__ Dp_)
{
    const int b = blockIdx.x;
    const int d = blockIdx.y * 256 + threadIdx.x;
    __shared__ float sB[SEQ][NSTATE];
    __shared__ float sC[SEQ][NSTATE];

    for (int i = threadIdx.x; i < SEQ * 2 * NSTATE; i += 256) {
        int t = i >> 5, j = i & 31;
        float v = g_xdbl[((size_t)(b * SEQ + t)) * 64 + 32 + j];
        if (j < 16) sB[t][j] = v; else sC[t][j - 16] = v;
    }
    __syncthreads();

    float rA[NSTATE];
    #pragma unroll
    for (int n = 0; n < NSTATE; n++) rA[n] = -expf(A_log[(size_t)d * NSTATE + n]);
    const float Dv = Dp_[d];
    float h[NSTATE];
    #pragma unroll
    for (int n = 0; n < NSTATE; n++) h[n] = 0.f;

    const size_t rowbase = (size_t)b * SEQ;
    for (int t = 0; t < SEQ; t++) {
        const size_t row = rowbase + t;
        float delta = g_delta[row * DINV + d];
        float u     = g_uc[row * DINV + d];
        float du    = delta * u;
        float y = 0.f;
        #pragma unroll
        for (int n = 0; n < NSTATE; n++) {
            float dA = __expf(delta * rA[n]);
            h[n] = dA * h[n] + du * sB[t][n];
            y += h[n] * sC[t][n];
        }
        float z = g_xz[row * XZW + DINV + d];
        float silu_z = z / (1.0f + __expf(-z));
        g_y[row * DINV + d] = (y + u * Dv) * silu_z;
    }
}

// ---------------- final LayerNorm stats ---------------------------------------
__global__ void __launch_bounds__(256) ln_stats_kernel()
{
    const int b = blockIdx.x;
    const float4* xp = (const float4*)(g_x + (size_t)b * HEADK);
    float s = 0.f, sq = 0.f;
    for (int i = threadIdx.x; i < HEADK / 4; i += 256) {
        float4 v = xp[i];
        s  += v.x + v.y + v.z + v.w;
        sq += v.x*v.x + v.y*v.y + v.z*v.z + v.w*v.w;
    }
    __shared__ float rs[256], rq[256];
    rs[threadIdx.x] = s; rq[threadIdx.x] = sq; __syncthreads();
    for (int st = 128; st > 0; st >>= 1) {
        if (threadIdx.x < st) { rs[threadIdx.x] += rs[threadIdx.x + st];
                                rq[threadIdx.x] += rq[threadIdx.x + st]; }
        __syncthreads();
    }
    if (threadIdx.x == 0) {
        float mu  = rs[0] / (float)HEADK;
        float var = rq[0] / (float)HEADK - mu * mu;
        g_stats[b] = make_float2(mu, rsqrtf(var + 1e-5f));
    }
}

// ---------------- head: split-K GEMM (LN fused on A load) --------------------
__global__ void __launch_bounds__(256) head_gemm_kernel(
    const float* __restrict__ lng, const float* __restrict__ lnb,
    const float* __restrict__ hw)
{
    constexpr int BK = 16;
    const int slab = blockIdx.x;
    const int kbeg = slab * (HEADK / HSLABS);
    __shared__ float sX[BK][BATCH];
    __shared__ float sW[BK][NCLS];
    const int tid = threadIdx.x;
    const int tx = tid & 15;
    const int ty = tid >> 4;

    float acc[8][2];
    #pragma unroll
    for (int i = 0; i < 8; i++) { acc[i][0] = 0.f; acc[i][1] = 0.f; }

    for (int k0 = kbeg; k0 < kbeg + HEADK / HSLABS; k0 += BK) {
        #pragma unroll
        for (int l = 0; l < 2; l++) {
            int idx = tid + l * 256;
            int row = idx >> 2, kq = (idx & 3) << 2;
            float2 st = g_stats[row];
            float4 v  = *(const float4*)(g_x + (size_t)row * HEADK + k0 + kq);
            float4 gg = *(const float4*)(lng + k0 + kq);
            float4 bb = *(const float4*)(lnb + k0 + kq);
            sX[kq + 0][row] = (v.x - st.x) * st.y * gg.x + bb.x;
            sX[kq + 1][row] = (v.y - st.x) * st.y * gg.y + bb.y;
            sX[kq + 2][row] = (v.z - st.x) * st.y * gg.z + bb.z;
            sX[kq + 3][row] = (v.w - st.x) * st.y * gg.w + bb.w;
        }
        if (tid < 128) {
            int row = tid >> 2, kq = (tid & 3) << 2;
            float4 v = *(const float4*)(hw + (size_t)row * HEADK + k0 + kq);
            sW[kq + 0][row] = v.x; sW[kq + 1][row] = v.y;
            sW[kq + 2][row] = v.z; sW[kq + 3][row] = v.w;
        }
        __syncthreads();
        #pragma unroll
        for (int kk = 0; kk < BK; kk++) {
            float w0 = sW[kk][tx * 2], w1 = sW[kk][tx * 2 + 1];
            #pragma unroll
            for (int i = 0; i < 8; i++) {
                float a = sX[kk][ty * 8 + i];
                acc[i][0] += a * w0;
                acc[i][1] += a * w1;
            }
        }
        __syncthreads();
    }
    #pragma unroll
    for (int i = 0; i < 8; i++) {
        int m = ty * 8 + i;
        g_hpart[((size_t)slab * BATCH + m) * NCLS + tx * 2 + 0] = acc[i][0];
        g_hpart[((size_t)slab * BATCH + m) * NCLS + tx * 2 + 1] = acc[i][1];
    }
}

__global__ void __launch_bounds__(256) head_reduce_kernel(
    const float* __restrict__ head_b, float* __restrict__ out)
{
    int idx = blockIdx.x * blockDim.x + threadIdx.x;
    if (idx < BATCH * NCLS) {
        float s = head_b[idx & (NCLS - 1)];
        for (int sl = 0; sl < HSLABS; sl++)
            s += g_hpart[(size_t)sl * BATCH * NCLS + idx];
        out[idx] = s;
    }
}

// ---------------- host orchestration -----------------------------------------
extern "C" void kernel_launch(void* const* d_in, const int* in_sizes, int n_in,
                              void* d_out, int out_size)
{
    const float* series    = (const float*)d_in[0];
    const float* seg_w     = (const float*)d_in[1];
    const float* seg_b     = (const float*)d_in[2];
    const float* ln_g      = (const float*)d_in[3];
    const float* ln_b      = (const float*)d_in[4];
    const float* in_proj_w = (const float*)d_in[5];
    const float* conv_w    = (const float*)d_in[6];
    const float* conv_b    = (const float*)d_in[7];
    const float* x_proj_w  = (const float*)d_in[8];
    const float* dt_proj_w = (const float*)d_in[9];
    const float* dt_proj_b = (const float*)d_in[10];
    const float* A_log     = (const float*)d_in[11];
    const float* Dw        = (const float*)d_in[12];
    const float* out_proj_w= (const float*)d_in[13];
    const float* hlng      = (const float*)d_in[14];
    const float* hlnb      = (const float*)d_in[15];
    const float* head_w    = (const float*)d_in[16];
    const float* head_b    = (const float*)d_in[17];
    float* out = (float*)d_out;

    float *px, *pxz, *puc, *pxdbl, *pdelta, *py;
    cudaGetSymbolAddress((void**)&px,     g_x);
    cudaGetSymbolAddress((void**)&pxz,    g_xz);
    cudaGetSymbolAddress((void**)&puc,    g_uc);
    cudaGetSymbolAddress((void**)&pxdbl,  g_xdbl);
    cudaGetSymbolAddress((void**)&pdelta, g_delta);
    cudaGetSymbolAddress((void**)&py,     g_y);

    // 1) segment linear + per-pathway LN -> g_x [8192, 512]
    seg_ln_kernel<<<dim3(NPATH, BATCH/4), 512>>>(series, seg_w, seg_b, ln_g, ln_b);

    for (int dep = 0; dep < DEPTHN; dep++) {
        // 2) in_proj (HMMA bf16x3): [8192,512] x [4096,512]^T -> g_xz
        hmma_gemm<128,2,4><<<dim3(XZW/128, ROWSZ/128), 256>>>(
            px, in_proj_w + (size_t)dep * XZW * DIMV, pxz,
            ROWSZ, XZW, DIMV, DIMV, DIMV);
        // 3) conv + silu -> g_uc
        conv_silu_kernel<<<(ROWSZ * (DINV/4)) / 256, 256>>>(
            conv_w + (size_t)dep * DINV * 4, conv_b + (size_t)dep * DINV);
        // 4) x_proj (HMMA bf16x3): [8192,1024] x [64,1024]^T -> g_xdbl
        hmma_gemm<64,4,2><<<dim3(1, ROWSZ/128), 256>>>(
            puc, x_proj_w + (size_t)dep * 64 * DINV, pxdbl,
            ROWSZ, 64, DINV, DINV, DINV);
        // 5) dt_proj + bias + softplus (FFMA; tiny K=32)
        gemm_nt<128,64,8,4,1><<<dim3(DINV/64, ROWSZ/128), 256>>>(
            pxdbl, dt_proj_w + (size_t)dep * DINV * DTRV,
            dt_proj_b + (size_t)dep * DINV, pdelta,
            ROWSZ, DINV, DTRV, 64);
        // 6) selective scan + D skip + silu(z) gate -> g_y
        scan_kernel<<<dim3(BATCH, DINV/256), 256>>>(
            A_log + (size_t)dep * DINV * NSTATE, Dw + (size_t)dep * DINV);
        // 7) out_proj (HMMA bf16x3): [8192,1024] x [512,1024]^T -> g_x
        hmma_gemm<128,2,4><<<dim3(DIMV/128, ROWSZ/128), 256>>>(
            py, out_proj_w + (size_t)dep * DIMV * DINV, px,
            ROWSZ, DIMV, DINV, DINV, DINV);
    }

    // 8) final LN stats + head GEMM (split-K) + deterministic reduce
    ln_stats_kernel<<<BATCH, 256>>>();
    head_gemm_kernel<<<HSLABS, 256>>>(hlng, hlnb, head_w);
    head_reduce_kernel<<<(BATCH*NCLS + 255)/256, 256>>>(head_b, out);
}

// round 4
// speedup vs baseline: 1.9830x; 1.2902x over previous
#include <cuda_runtime.h>
#include <cuda_bf16.h>
#include <math.h>
#include <stdint.h>

// Problem constants
#define BATCH   128
#define NPATH   64
#define PLEN    128
#define DIMV    512
#define NSTATE  16
#define DEPTHN  2
#define DINV    1024
#define DTRV    32
#define NCLS    32
#define SEQ     64
#define ROWSZ   (BATCH*SEQ)        // 8192
#define XZW     (2*DINV)           // 4096
#define HEADK   (NPATH*DIMV)       // 32768
#define HSLABS  64

// ---------------- scratch (static device globals; no allocation) -------------
__device__ float  g_x[(size_t)ROWSZ*DIMV];
__device__ float  g_xz[(size_t)ROWSZ*XZW];
__device__ float  g_uc[(size_t)ROWSZ*DINV];
__device__ float  g_xdbl[(size_t)ROWSZ*64];
__device__ float  g_delta[(size_t)ROWSZ*DINV];
__device__ float  g_y[(size_t)ROWSZ*DINV];
__device__ float2 g_stats[BATCH];
__device__ float  g_hpart[(size_t)HSLABS*BATCH*NCLS];
// bf16 hi/lo split buffers
__device__ __nv_bfloat16 g_ah[(size_t)ROWSZ*DINV];   // activations hi (16MB)
__device__ __nv_bfloat16 g_al[(size_t)ROWSZ*DINV];   // activations lo
__device__ __nv_bfloat16 g_wh[(size_t)XZW*DIMV];     // weights hi (4MB)
__device__ __nv_bfloat16 g_wl[(size_t)XZW*DIMV];     // weights lo

__device__ __forceinline__ float softplusf(float x) {
    return fmaxf(x, 0.0f) + log1pf(expf(-fabsf(x)));
}

// split fp32 -> (hi, lo) bf16 pairs, packed 2x16b per u32
__device__ __forceinline__ void cvt_hl(float4 v, uint2& hw, uint2& lw) {
    float f[4] = {v.x, v.y, v.z, v.w};
    unsigned short h[4], l[4];
    #pragma unroll
    for (int i = 0; i < 4; i++) {
        __nv_bfloat16 hb = __float2bfloat16_rn(f[i]);
        h[i] = __bfloat16_as_ushort(hb);
        float r = f[i] - __bfloat162float(hb);
        l[i] = __bfloat16_as_ushort(__float2bfloat16_rn(r));
    }
    hw.x = (uint32_t)h[0] | ((uint32_t)h[1] << 16);
    hw.y = (uint32_t)h[2] | ((uint32_t)h[3] << 16);
    lw.x = (uint32_t)l[0] | ((uint32_t)l[1] << 16);
    lw.y = (uint32_t)l[2] | ((uint32_t)l[3] << 16);
}

__global__ void __launch_bounds__(256) split_kernel(
    const float* __restrict__ src, __nv_bfloat16* __restrict__ hi,
    __nv_bfloat16* __restrict__ lo, int n4)
{
    int i = blockIdx.x * blockDim.x + threadIdx.x;
    if (i < n4) {
        float4 v = ((const float4*)src)[i];
        uint2 hw, lw; cvt_hl(v, hw, lw);
        ((uint2*)hi)[i] = hw;
        ((uint2*)lo)[i] = lw;
    }
}

__device__ __forceinline__ void mma16816(float* c, const uint32_t* a, const uint32_t* b) {
    asm volatile(
        "mma.sync.aligned.m16n8k16.row.col.f32.bf16.bf16.f32 "
        "{%0,%1,%2,%3}, {%4,%5,%6,%7}, {%8,%9}, {%0,%1,%2,%3};"
        : "+f"(c[0]), "+f"(c[1]), "+f"(c[2]), "+f"(c[3])
        : "r"(a[0]), "r"(a[1]), "r"(a[2]), "r"(a[3]), "r"(b[0]), "r"(b[1]));
}

__device__ __forceinline__ void cp16(uint32_t dst, const void* src) {
    asm volatile("cp.async.cg.shared.global [%0], [%1], 16;" :: "r"(dst), "l"(src));
}
__device__ __forceinline__ void cp_commit() {
    asm volatile("cp.async.commit_group;" ::: "memory");
}
template<int N>
__device__ __forceinline__ void cp_wait() {
    asm volatile("cp.async.wait_group %0;" :: "n"(N) : "memory");
}

// =============== HMMA bf16x3 GEMM (pre-split inputs, cp.async pipeline) ======
// C[M,N] = A[M,K]*W[N,K]^T where A = Ah+Al, W = Wh+Wl (bf16), fp32 accum,
// 3 passes AhWh + AhWl + AlWh. Block tile BM x BN, BK=32, 2-stage cp.async.
template<int BM, int BN, int WM, int WN>
__global__ void __launch_bounds__(256, 2) hmma_gemm(
    const __nv_bfloat16* __restrict__ Ah, const __nv_bfloat16* __restrict__ Al,
    const __nv_bfloat16* __restrict__ Wh, const __nv_bfloat16* __restrict__ Wl,
    float* __restrict__ C, int M, int N, int K, int lda, int ldb)
{
    constexpr int BK = 32, SA = 40;                 // 80B row stride, conflict-free
    constexpr int WTM = BM / WM, WTN = BN / WN;
    constexpr int MF = WTM / 16, NF = WTN / 8;
    static_assert(WM * WN == 8, "8 warps");
    constexpr int AOFF = 0, ALOFF = BM * SA, WOFF = 2 * BM * SA,
                  WLOFF = 2 * BM * SA + BN * SA;
    constexpr int STG = (2 * BM + 2 * BN) * SA;     // elems per stage

    extern __shared__ __nv_bfloat16 smem[];
    uint32_t sbase;
    asm("{ .reg .u64 t; cvta.to.shared.u64 t, %1; cvt.u32.u64 %0, t; }"
        : "=r"(sbase) : "l"(smem));

    const int tid = threadIdx.x, lane = tid & 31, wid = tid >> 5;
    const int warpM = wid % WM, warpN = wid / WM;
    const int m0 = blockIdx.y * BM, n0 = blockIdx.x * BN;
    const int g = lane >> 2, c2 = (lane & 3) * 2;
    const int mbase = warpM * WTM, nbase = warpN * WTN;

    float acc[MF][NF][4];
    #pragma unroll
    for (int mi = 0; mi < MF; mi++)
        #pragma unroll
        for (int ni = 0; ni < NF; ni++)
            #pragma unroll
            for (int q = 0; q < 4; q++) acc[mi][ni][q] = 0.f;

    const int NC = K / BK;

    auto load_chunk = [&](int c, int s) {
        const int kc = c * BK;
        const uint32_t st = sbase + (uint32_t)s * STG * 2;
        #pragma unroll
        for (int it = 0; it < (BM * 4 + 255) / 256; it++) {
            int i = tid + it * 256;
            if ((BM * 4) % 256 == 0 || i < BM * 4) {
                int r = i >> 2, q = i & 3;
                uint32_t d = st + (uint32_t)r * 80 + q * 16;
                const size_t go = (size_t)(m0 + r) * lda + kc + q * 8;
                cp16(d + AOFF * 2,  Ah + go);
                cp16(d + ALOFF * 2, Al + go);
            }
        }
        #pragma unroll
        for (int it = 0; it < (BN * 4 + 255) / 256; it++) {
            int i = tid + it * 256;
            if ((BN * 4) % 256 == 0 || i < BN * 4) {
                int r = i >> 2, q = i & 3;
                uint32_t d = st + (uint32_t)r * 80 + q * 16;
                const size_t go = (size_t)(n0 + r) * ldb + kc + q * 8;
                cp16(d + WOFF * 2,  Wh + go);
                cp16(d + WLOFF * 2, Wl + go);
            }
        }
    };

    load_chunk(0, 0);
    cp_commit();

    for (int c = 0; c < NC; c++) {
        const int s = c & 1;
        if (c + 1 < NC) {
            load_chunk(c + 1, (c + 1) & 1);
            cp_commit();
            cp_wait<1>();
        } else {
            cp_wait<0>();
        }
        __syncthreads();

        const __nv_bfloat16* sAh = smem + s * STG + AOFF;
        const __nv_bfloat16* sAl = smem + s * STG + ALOFF;
        const __nv_bfloat16* sWh = smem + s * STG + WOFF;
        const __nv_bfloat16* sWl = smem + s * STG + WLOFF;

        #pragma unroll
        for (int ks = 0; ks < BK; ks += 16) {
            uint32_t ah[MF][4], al[MF][4], bh[NF][2], bl[NF][2];
            #pragma unroll
            for (int mi = 0; mi < MF; mi++) {
                int r0 = (mbase + mi * 16 + g) * SA + ks + c2;
                int r8 = r0 + 8 * SA;
                ah[mi][0] = *(const uint32_t*)&sAh[r0];
                ah[mi][1] = *(const uint32_t*)&sAh[r8];
                ah[mi][2] = *(const uint32_t*)&sAh[r0 + 8];
                ah[mi][3] = *(const uint32_t*)&sAh[r8 + 8];
            }
            #pragma unroll
            for (int ni = 0; ni < NF; ni++) {
                int rn = (nbase + ni * 8 + g) * SA + ks + c2;
                bh[ni][0] = *(const uint32_t*)&sWh[rn];
                bh[ni][1] = *(const uint32_t*)&sWh[rn + 8];
            }
            #pragma unroll
            for (int mi = 0; mi < MF; mi++)
                #pragma unroll
                for (int ni = 0; ni < NF; ni++)
                    mma16816(acc[mi][ni], ah[mi], bh[ni]);
            #pragma unroll
            for (int ni = 0; ni < NF; ni++) {
                int rn = (nbase + ni * 8 + g) * SA + ks + c2;
                bl[ni][0] = *(const uint32_t*)&sWl[rn];
                bl[ni][1] = *(const uint32_t*)&sWl[rn + 8];
            }
            #pragma unroll
            for (int mi = 0; mi < MF; mi++)
                #pragma unroll
                for (int ni = 0; ni < NF; ni++)
                    mma16816(acc[mi][ni], ah[mi], bl[ni]);
            #pragma unroll
            for (int mi = 0; mi < MF; mi++) {
                int r0 = (mbase + mi * 16 + g) * SA + ks + c2;
                int r8 = r0 + 8 * SA;
                al[mi][0] = *(const uint32_t*)&sAl[r0];
                al[mi][1] = *(const uint32_t*)&sAl[r8];
                al[mi][2] = *(const uint32_t*)&sAl[r0 + 8];
                al[mi][3] = *(const uint32_t*)&sAl[r8 + 8];
            }
            #pragma unroll
            for (int mi = 0; mi < MF; mi++)
                #pragma unroll
                for (int ni = 0; ni < NF; ni++)
                    mma16816(acc[mi][ni], al[mi], bh[ni]);
        }
        __syncthreads();
    }

    #pragma unroll
    for (int mi = 0; mi < MF; mi++) {
        int row = m0 + mbase + mi * 16 + g;
        #pragma unroll
        for (int ni = 0; ni < NF; ni++) {
            int col = n0 + nbase + ni * 8 + c2;
            *(float2*)(C + (size_t)row * N + col)
                = make_float2(acc[mi][ni][0], acc[mi][ni][1]);
            *(float2*)(C + (size_t)(row + 8) * N + col)
                = make_float2(acc[mi][ni][2], acc[mi][ni][3]);
        }
    }
}

// ---------------- stage 1: per-pathway linear + LayerNorm --------------------
__global__ void __launch_bounds__(512) seg_ln_kernel(
    const float* __restrict__ series, const float* __restrict__ seg_w,
    const float* __restrict__ seg_b,  const float* __restrict__ ln_g,
    const float* __restrict__ ln_b)
{
    const int n  = blockIdx.x;
    const int b0 = blockIdx.y * 4;
    const int d  = threadIdx.x;
    __shared__ float s_s[4][PLEN];
    __shared__ float s_red[512];

    {
        int r = d >> 7, p = d & 127;
        s_s[r][p] = series[(size_t)(b0 + r) * (NPATH*PLEN) + n * PLEN + p];
    }
    __syncthreads();

    float sb = seg_b[n*DIMV + d];
    float acc0 = sb, acc1 = sb, acc2 = sb, acc3 = sb;
    const float* wp = seg_w + (size_t)n * PLEN * DIMV + d;
    #pragma unroll 4
    for (int p = 0; p < PLEN; p++) {
        float w = wp[(size_t)p * DIMV];
        acc0 += s_s[0][p] * w;
        acc1 += s_s[1][p] * w;
        acc2 += s_s[2][p] * w;
        acc3 += s_s[3][p] * w;
    }
    float gam = ln_g[n*DIMV + d], bet = ln_b[n*DIMV + d];
    float accs[4] = {acc0, acc1, acc2, acc3};
    #pragma unroll
    for (int r = 0; r < 4; r++) {
        float v = accs[r];
        s_red[d] = v; __syncthreads();
        for (int s = 256; s > 0; s >>= 1) {
            if (d < s) s_red[d] += s_red[d + s];
            __syncthreads();
        }
        float mu = s_red[0] * (1.0f / DIMV);
        __syncthreads();
        float c = v - mu;
        s_red[d] = c * c; __syncthreads();
        for (int s = 256; s > 0; s >>= 1) {
            if (d < s) s_red[d] += s_red[d + s];
            __syncthreads();
        }
        float var = s_red[0] * (1.0f / DIMV);
        __syncthreads();
        float rstd = rsqrtf(var + 1e-5f);
        g_x[((size_t)(b0 + r) * NPATH + n) * DIMV + d] = c * rstd * gam + bet;
    }
}

// ---------------- FFMA GEMM (kept for the tiny dt_proj) ----------------------
template<int BM, int BN, int TM, int TN, int EPI>
__global__ void __launch_bounds__(256) gemm_nt(
    const float* __restrict__ A, const float* __restrict__ Bw,
    const float* __restrict__ bias, float* __restrict__ C,
    int M, int N, int K, int lda)
{
    constexpr int BK = 16;
    __shared__ float As[BK][BM];
    __shared__ float Bs[BK][BN];
    const int tid = threadIdx.x;
    const int m0 = blockIdx.y * BM;
    const int n0 = blockIdx.x * BN;
    constexpr int NTX = BN / TN;
    static_assert((BM / TM) * (BN / TN) == 256, "thread tiling");
    const int tx = tid % NTX;
    const int ty = tid / NTX;

    float acc[TM][TN];
    #pragma unroll
    for (int i = 0; i < TM; i++)
        #pragma unroll
        for (int j = 0; j < TN; j++) acc[i][j] = 0.f;

    constexpr int A_F4 = BM * 4;
    constexpr int B_F4 = BN * 4;

    for (int k0 = 0; k0 < K; k0 += BK) {
        #pragma unroll
        for (int l = 0; l < (A_F4 + 255) / 256; l++) {
            int idx = tid + l * 256;
            if ((A_F4 % 256) == 0 || idx < A_F4) {
                int row = idx >> 2, kq = (idx & 3) << 2;
                float4 v = *(const float4*)(A + (size_t)(m0 + row) * lda + k0 + kq);
                As[kq + 0][row] = v.x; As[kq + 1][row] = v.y;
                As[kq + 2][row] = v.z; As[kq + 3][row] = v.w;
            }
        }
        #pragma unroll
        for (int l = 0; l < (B_F4 + 255) / 256; l++) {
            int idx = tid + l * 256;
            if ((B_F4 % 256) == 0 || idx < B_F4) {
                int row = idx >> 2, kq = (idx & 3) << 2;
                float4 v = *(const float4*)(Bw + (size_t)(n0 + row) * K + k0 + kq);
                Bs[kq + 0][row] = v.x; Bs[kq + 1][row] = v.y;
                Bs[kq + 2][row] = v.z; Bs[kq + 3][row] = v.w;
            }
        }
        __syncthreads();
        #pragma unroll
        for (int kk = 0; kk < BK; kk++) {
            float a[TM], bfr[TN];
            #pragma unroll
            for (int i = 0; i < TM; i++) a[i] = As[kk][ty * TM + i];
            #pragma unroll
            for (int j = 0; j < TN; j++) bfr[j] = Bs[kk][tx * TN + j];
            #pragma unroll
            for (int i = 0; i < TM; i++)
                #pragma unroll
                for (int j = 0; j < TN; j++) acc[i][j] += a[i] * bfr[j];
        }
        __syncthreads();
    }

    #pragma unroll
    for (int i = 0; i < TM; i++) {
        int m = m0 + ty * TM + i;
        #pragma unroll
        for (int j = 0; j < TN; j++) {
            int n = n0 + tx * TN + j;
            float v = acc[i][j];
            if (EPI == 1) v = softplusf(v + bias[n]);
            C[(size_t)m * N + n] = v;
        }
    }
}

// ---------------- causal depthwise conv (k=4) + bias + silu ------------------
__global__ void __launch_bounds__(256) conv_silu_kernel(
    const float* __restrict__ cw, const float* __restrict__ cb)
{
    int idx = blockIdx.x * blockDim.x + threadIdx.x;
    int c4  = (idx & (DINV/4 - 1)) << 2;
    int row = idx >> 8;
    int t   = row & (SEQ - 1);
    const float* urow = g_xz + (size_t)row * XZW + c4;

    float4 w0 = *(const float4*)(cw + (size_t)(c4 + 0) * 4);
    float4 w1 = *(const float4*)(cw + (size_t)(c4 + 1) * 4);
    float4 w2 = *(const float4*)(cw + (size_t)(c4 + 2) * 4);
    float4 w3 = *(const float4*)(cw + (size_t)(c4 + 3) * 4);
    float4 a  = *(const float4*)(cb + c4);

    if (t - 3 >= 0) {
        float4 u = *(const float4*)(urow - (size_t)3 * XZW);
        a.x += u.x * w0.x; a.y += u.y * w1.x; a.z += u.z * w2.x; a.w += u.w * w3.x;
    }
    if (t - 2 >= 0) {
        float4 u = *(const float4*)(urow - (size_t)2 * XZW);
        a.x += u.x * w0.y; a.y += u.y * w1.y; a.z += u.z * w2.y; a.w += u.w * w3.y;
    }
    if (t - 1 >= 0) {
        float4 u = *(const float4*)(urow - (size_t)1 * XZW);
        a.x += u.x * w0.z; a.y += u.y * w1.z; a.z += u.z * w2.z; a.w += u.w * w3.z;
    }
    {
        float4 u = *(const float4*)(urow);
        a.x += u.x * w0.w; a.y += u.y * w1.w; a.z += u.z * w2.w; a.w += u.w * w3.w;
    }
    a.x = a.x / (1.0f + __expf(-a.x));
    a.y = a.y / (1.0f + __expf(-a.y));
    a.z = a.z / (1.0f + __expf(-a.z));
    a.w = a.w / (1.0f + __expf(-a.w));
    *(float4*)(g_uc + (size_t)row * DINV + c4) = a;
}

// ---------------- selective scan + gating epilogue ----------------------------
__global__ void __launch_bounds__(256) scan_kernel(
    const float* __restrict__ A_log, const float* __restrict__ Dp_)
{
    const int b = blockIdx.x;
    const int d = blockIdx.y * 256 + threadIdx.x;
    __shared__ float sB[SEQ][NSTATE];
    __shared__ float sC[SEQ][NSTATE];

    for (int i = threadIdx.x; i < SEQ * 2 * NSTATE; i += 256) {
        int t = i >> 5, j = i & 31;
        float v = g_xdbl[((size_t)(b * SEQ + t)) * 64 + 32 + j];
        if (j < 16) sB[t][j] = v; else sC[t][j - 16] = v;
    }
    __syncthreads();

    float rA[NSTATE];
    #pragma unroll
    for (int n = 0; n < NSTATE; n++) rA[n] = -expf(A_log[(size_t)d * NSTATE + n]);
    const float Dv = Dp_[d];
    float h[NSTATE];
    #pragma unroll
    for (int n = 0; n < NSTATE; n++) h[n] = 0.f;

    const size_t rowbase = (size_t)b * SEQ;
    for (int t = 0; t < SEQ; t++) {
        const size_t row = rowbase + t;
        float delta = g_delta[row * DINV + d];
        float u     = g_uc[row * DINV + d];
        float du    = delta * u;
        float y = 0.f;
        #pragma unroll
        for (int n = 0; n < NSTATE; n++) {
            float dA = __expf(delta * rA[n]);
            h[n] = dA * h[n] + du * sB[t][n];
            y += h[n] * sC[t][n];
        }
        float z = g_xz[row * XZW + DINV + d];
        float silu_z = z / (1.0f + __expf(-z));
        g_y[row * DINV + d] = (y + u * Dv) * silu_z;
    }
}

// ---------------- final LayerNorm stats ---------------------------------------
__global__ void __launch_bounds__(256) ln_stats_kernel()
{
    const int b = blockIdx.x;
    const float4* xp = (const float4*)(g_x + (size_t)b * HEADK);
    float s = 0.f, sq = 0.f;
    for (int i = threadIdx.x; i < HEADK / 4; i += 256) {
        float4 v = xp[i];
        s  += v.x + v.y + v.z + v.w;
        sq += v.x*v.x + v.y*v.y + v.z*v.z + v.w*v.w;
    }
    __shared__ float rs[256], rq[256];
    rs[threadIdx.x] = s; rq[threadIdx.x] = sq; __syncthreads();
    for (int st = 128; st > 0; st >>= 1) {
        if (threadIdx.x < st) { rs[threadIdx.x] += rs[threadIdx.x + st];
                                rq[threadIdx.x] += rq[threadIdx.x + st]; }
        __syncthreads();
    }
    if (threadIdx.x == 0) {
        float mu  = rs[0] / (float)HEADK;
        float var = rq[0] / (float)HEADK - mu * mu;
        g_stats[b] = make_float2(mu, rsqrtf(var + 1e-5f));
    }
}

// ---------------- head: split-K GEMM (LN fused on A load) --------------------
__global__ void __launch_bounds__(256) head_gemm_kernel(
    const float* __restrict__ lng, const float* __restrict__ lnb,
    const float* __restrict__ hw)
{
    constexpr int BK = 16;
    const int slab = blockIdx.x;
    const int kbeg = slab * (HEADK / HSLABS);
    __shared__ float sX[BK][BATCH];
    __shared__ float sW[BK][NCLS];
    const int tid = threadIdx.x;
    const int tx = tid & 15;
    const int ty = tid >> 4;

    float acc[8][2];
    #pragma unroll
    for (int i = 0; i < 8; i++) { acc[i][0] = 0.f; acc[i][1] = 0.f; }

    for (int k0 = kbeg; k0 < kbeg + HEADK / HSLABS; k0 += BK) {
        #pragma unroll
        for (int l = 0; l < 2; l++) {
            int idx = tid + l * 256;
            int row = idx >> 2, kq = (idx & 3) << 2;
            float2 st = g_stats[row];
            float4 v  = *(const float4*)(g_x + (size_t)row * HEADK + k0 + kq);
            float4 gg = *(const float4*)(lng + k0 + kq);
            float4 bb = *(const float4*)(lnb + k0 + kq);
            sX[kq + 0][row] = (v.x - st.x) * st.y * gg.x + bb.x;
            sX[kq + 1][row] = (v.y - st.x) * st.y * gg.y + bb.y;
            sX[kq + 2][row] = (v.z - st.x) * st.y * gg.z + bb.z;
            sX[kq + 3][row] = (v.w - st.x) * st.y * gg.w + bb.w;
        }
        if (tid < 128) {
            int row = tid >> 2, kq = (tid & 3) << 2;
            float4 v = *(const float4*)(hw + (size_t)row * HEADK + k0 + kq);
            sW[kq + 0][row] = v.x; sW[kq + 1][row] = v.y;
            sW[kq + 2][row] = v.z; sW[kq + 3][row] = v.w;
        }
        __syncthreads();
        #pragma unroll
        for (int kk = 0; kk < BK; kk++) {
            float w0 = sW[kk][tx * 2], w1 = sW[kk][tx * 2 + 1];
            #pragma unroll
            for (int i = 0; i < 8; i++) {
                float a = sX[kk][ty * 8 + i];
                acc[i][0] += a * w0;
                acc[i][1] += a * w1;
            }
        }
        __syncthreads();
    }
    #pragma unroll
    for (int i = 0; i < 8; i++) {
        int m = ty * 8 + i;
        g_hpart[((size_t)slab * BATCH + m) * NCLS + tx * 2 + 0] = acc[i][0];
        g_hpart[((size_t)slab * BATCH + m) * NCLS + tx * 2 + 1] = acc[i][1];
    }
}

__global__ void __launch_bounds__(256) head_reduce_kernel(
    const float* __restrict__ head_b, float* __restrict__ out)
{
    int idx = blockIdx.x * blockDim.x + threadIdx.x;
    if (idx < BATCH * NCLS) {
        float s = head_b[idx & (NCLS - 1)];
        for (int sl = 0; sl < HSLABS; sl++)
            s += g_hpart[(size_t)sl * BATCH * NCLS + idx];
        out[idx] = s;
    }
}

// ---------------- host orchestration -----------------------------------------
extern "C" void kernel_launch(void* const* d_in, const int* in_sizes, int n_in,
                              void* d_out, int out_size)
{
    const float* series    = (const float*)d_in[0];
    const float* seg_w     = (const float*)d_in[1];
    const float* seg_b     = (const float*)d_in[2];
    const float* ln_g      = (const float*)d_in[3];
    const float* ln_b      = (const float*)d_in[4];
    const float* in_proj_w = (const float*)d_in[5];
    const float* conv_w    = (const float*)d_in[6];
    const float* conv_b    = (const float*)d_in[7];
    const float* x_proj_w  = (const float*)d_in[8];
    const float* dt_proj_w = (const float*)d_in[9];
    const float* dt_proj_b = (const float*)d_in[10];
    const float* A_log     = (const float*)d_in[11];
    const float* Dw        = (const float*)d_in[12];
    const float* out_proj_w= (const float*)d_in[13];
    const float* hlng      = (const float*)d_in[14];
    const float* hlnb      = (const float*)d_in[15];
    const float* head_w    = (const float*)d_in[16];
    const float* head_b    = (const float*)d_in[17];
    float* out = (float*)d_out;

    float *px, *pxz, *puc, *pxdbl, *pdelta, *py;
    __nv_bfloat16 *pah, *pal, *pwh, *pwl;
    cudaGetSymbolAddress((void**)&px,     g_x);
    cudaGetSymbolAddress((void**)&pxz,    g_xz);
    cudaGetSymbolAddress((void**)&puc,    g_uc);
    cudaGetSymbolAddress((void**)&pxdbl,  g_xdbl);
    cudaGetSymbolAddress((void**)&pdelta, g_delta);
    cudaGetSymbolAddress((void**)&py,     g_y);
    cudaGetSymbolAddress((void**)&pah,    g_ah);
    cudaGetSymbolAddress((void**)&pal,    g_al);
    cudaGetSymbolAddress((void**)&pwh,    g_wh);
    cudaGetSymbolAddress((void**)&pwl,    g_wl);

    // dynamic smem: 2 stages x (2*BM + 2*BN) * 40 elems * 2B
    const int SMEM128 = 2 * (2*128 + 2*128) * 40 * 2;  // 81920
    const int SMEM64  = 2 * (2*64  + 2*64 ) * 40 * 2;  // 40960
    cudaFuncSetAttribute((const void*)hmma_gemm<128,128,2,4>,
                         cudaFuncAttributeMaxDynamicSharedMemorySize, SMEM128);
    cudaFuncSetAttribute((const void*)hmma_gemm<64,64,2,4>,
                         cudaFuncAttributeMaxDynamicSharedMemorySize, SMEM64);

    auto split = [](const float* src, __nv_bfloat16* hi, __nv_bfloat16* lo, int n) {
        split_kernel<<<(n/4 + 255)/256, 256>>>(src, hi, lo, n/4);
    };

    // 1) segment linear + per-pathway LN -> g_x [8192, 512]
    seg_ln_kernel<<<dim3(NPATH, BATCH/4), 512>>>(series, seg_w, seg_b, ln_g, ln_b);

    for (int dep = 0; dep < DEPTHN; dep++) {
        // 2) in_proj: split inputs, then HMMA [8192,512]x[4096,512]^T -> g_xz
        split(px, pah, pal, ROWSZ * DIMV);
        split(in_proj_w + (size_t)dep * XZW * DIMV, pwh, pwl, XZW * DIMV);
        hmma_gemm<128,128,2,4><<<dim3(XZW/128, ROWSZ/128), 256, SMEM128>>>(
            pah, pal, pwh, pwl, pxz, ROWSZ, XZW, DIMV, DIMV, DIMV);
        // 3) conv + silu -> g_uc
        conv_silu_kernel<<<(ROWSZ * (DINV/4)) / 256, 256>>>(
            conv_w + (size_t)dep * DINV * 4, conv_b + (size_t)dep * DINV);
        // 4) x_proj: [8192,1024]x[64,1024]^T -> g_xdbl
        split(puc, pah, pal, ROWSZ * DINV);
        split(x_proj_w + (size_t)dep * 64 * DINV, pwh, pwl, 64 * DINV);
        hmma_gemm<64,64,2,4><<<dim3(1, ROWSZ/64), 256, SMEM64>>>(
            pah, pal, pwh, pwl, pxdbl, ROWSZ, 64, DINV, DINV, DINV);
        // 5) dt_proj + bias + softplus (FFMA; tiny K=32)
        gemm_nt<128,64,8,4,1><<<dim3(DINV/64, ROWSZ/128), 256>>>(
            pxdbl, dt_proj_w + (size_t)dep * DINV * DTRV,
            dt_proj_b + (size_t)dep * DINV, pdelta,
            ROWSZ, DINV, DTRV, 64);
        // 6) selective scan + D skip + silu(z) gate -> g_y
        scan_kernel<<<dim3(BATCH, DINV/256), 256>>>(
            A_log + (size_t)dep * DINV * NSTATE, Dw + (size_t)dep * DINV);
        // 7) out_proj: [8192,1024]x[512,1024]^T -> g_x
        split(py, pah, pal, ROWSZ * DINV);
        split(out_proj_w + (size_t)dep * DIMV * DINV, pwh, pwl, DIMV * DINV);
        hmma_gemm<128,128,2,4><<<dim3(DIMV/128, ROWSZ/128), 256, SMEM128>>>(
            pah, pal, pwh, pwl, px, ROWSZ, DIMV, DINV, DINV, DINV);
    }

    // 8) final LN stats + head GEMM (split-K) + deterministic reduce
    ln_stats_kernel<<<BATCH, 256>>>();
    head_gemm_kernel<<<HSLABS, 256>>>(hlng, hlnb, head_w);
    head_reduce_kernel<<<(BATCH*NCLS + 255)/256, 256>>>(head_b, out);
}

// round 5
// speedup vs baseline: 2.0871x; 1.0525x over previous
#include <cuda_runtime.h>
#include <cuda_bf16.h>
#include <math.h>
#include <stdint.h>

// Problem constants
#define BATCH   128
#define NPATH   64
#define PLEN    128
#define DIMV    512
#define NSTATE  16
#define DEPTHN  2
#define DINV    1024
#define DTRV    32
#define NCLS    32
#define SEQ     64
#define ROWSZ   (BATCH*SEQ)        // 8192
#define XZW     (2*DINV)           // 4096
#define HEADK   (NPATH*DIMV)       // 32768
#define HSLABS  64

// ---------------- scratch (static device globals; no allocation) -------------
__device__ float  g_x[(size_t)ROWSZ*DIMV];
__device__ float  g_xz[(size_t)ROWSZ*XZW];
__device__ float  g_uc[(size_t)ROWSZ*DINV];
__device__ float  g_xdbl[(size_t)ROWSZ*64];
__device__ float  g_delta[(size_t)ROWSZ*DINV];
__device__ float2 g_stats[BATCH];
__device__ float  g_hpart[(size_t)HSLABS*BATCH*NCLS];
// bf16 hi/lo split buffers: pair A (in_proj input / uc), pair B (scan y)
__device__ __nv_bfloat16 g_ah[(size_t)ROWSZ*DINV];
__device__ __nv_bfloat16 g_al[(size_t)ROWSZ*DINV];
__device__ __nv_bfloat16 g_bh[(size_t)ROWSZ*DINV];
__device__ __nv_bfloat16 g_bl[(size_t)ROWSZ*DINV];
__device__ __nv_bfloat16 g_wh[(size_t)XZW*DIMV];
__device__ __nv_bfloat16 g_wl[(size_t)XZW*DIMV];

__device__ __forceinline__ float softplusf(float x) {
    return fmaxf(x, 0.0f) + log1pf(expf(-fabsf(x)));
}

__device__ __forceinline__ void cvt_hl(float4 v, uint2& hw, uint2& lw) {
    float f[4] = {v.x, v.y, v.z, v.w};
    unsigned short h[4], l[4];
    #pragma unroll
    for (int i = 0; i < 4; i++) {
        __nv_bfloat16 hb = __float2bfloat16_rn(f[i]);
        h[i] = __bfloat16_as_ushort(hb);
        float r = f[i] - __bfloat162float(hb);
        l[i] = __bfloat16_as_ushort(__float2bfloat16_rn(r));
    }
    hw.x = (uint32_t)h[0] | ((uint32_t)h[1] << 16);
    hw.y = (uint32_t)h[2] | ((uint32_t)h[3] << 16);
    lw.x = (uint32_t)l[0] | ((uint32_t)l[1] << 16);
    lw.y = (uint32_t)l[2] | ((uint32_t)l[3] << 16);
}

__device__ __forceinline__ void pack2(float v0, float v1, uint32_t& hw, uint32_t& lw) {
    __nv_bfloat16 h0 = __float2bfloat16_rn(v0);
    __nv_bfloat16 h1 = __float2bfloat16_rn(v1);
    float r0 = v0 - __bfloat162float(h0), r1 = v1 - __bfloat162float(h1);
    hw = (uint32_t)__bfloat16_as_ushort(h0) | ((uint32_t)__bfloat16_as_ushort(h1) << 16);
    lw = (uint32_t)__bfloat16_as_ushort(__float2bfloat16_rn(r0))
       | ((uint32_t)__bfloat16_as_ushort(__float2bfloat16_rn(r1)) << 16);
}

__global__ void __launch_bounds__(256) split_kernel(
    const float* __restrict__ src, __nv_bfloat16* __restrict__ hi,
    __nv_bfloat16* __restrict__ lo, int n4)
{
    int i = blockIdx.x * blockDim.x + threadIdx.x;
    if (i < n4) {
        float4 v = ((const float4*)src)[i];
        uint2 hw, lw; cvt_hl(v, hw, lw);
        ((uint2*)hi)[i] = hw;
        ((uint2*)lo)[i] = lw;
    }
}

__device__ __forceinline__ void mma16816(float* c, const uint32_t* a, const uint32_t* b) {
    asm volatile(
        "mma.sync.aligned.m16n8k16.row.col.f32.bf16.bf16.f32 "
        "{%0,%1,%2,%3}, {%4,%5,%6,%7}, {%8,%9}, {%0,%1,%2,%3};"
        : "+f"(c[0]), "+f"(c[1]), "+f"(c[2]), "+f"(c[3])
        : "r"(a[0]), "r"(a[1]), "r"(a[2]), "r"(a[3]), "r"(b[0]), "r"(b[1]));
}
__device__ __forceinline__ void ldsm4(uint32_t* r, uint32_t addr) {
    asm volatile("ldmatrix.sync.aligned.m8n8.x4.shared.b16 {%0,%1,%2,%3}, [%4];"
        : "=r"(r[0]), "=r"(r[1]), "=r"(r[2]), "=r"(r[3]) : "r"(addr));
}
__device__ __forceinline__ void cp16(uint32_t dst, const void* src) {
    asm volatile("cp.async.cg.shared.global [%0], [%1], 16;" :: "r"(dst), "l"(src));
}
__device__ __forceinline__ void cp_commit() {
    asm volatile("cp.async.commit_group;" ::: "memory");
}
template<int N>
__device__ __forceinline__ void cp_wait() {
    asm volatile("cp.async.wait_group %0;" :: "n"(N) : "memory");
}

// =============== HMMA bf16x3 GEMM (ldmatrix + cp.async pipeline) =============
// C[M,N] = (Ah+Al)(Wh+Wl)^T, fp32 accum, 3 passes. Optional split epilogue
// writes Chi/Clo bf16 alongside fp32 C.
template<int BM, int BN, int WM, int WN, bool WSPLIT>
__global__ void __launch_bounds__(256, 2) hmma_gemm(
    const __nv_bfloat16* __restrict__ Ah, const __nv_bfloat16* __restrict__ Al,
    const __nv_bfloat16* __restrict__ Wh, const __nv_bfloat16* __restrict__ Wl,
    float* __restrict__ C, __nv_bfloat16* __restrict__ Chi,
    __nv_bfloat16* __restrict__ Clo, int M, int N, int K, int lda, int ldb)
{
    constexpr int BK = 32, SA = 40;                 // 80B row stride
    constexpr int WTM = BM / WM, WTN = BN / WN;
    constexpr int MF = WTM / 16, NF = WTN / 8;
    static_assert(WM * WN == 8, "8 warps");
    static_assert(NF % 2 == 0, "NF even for paired ldmatrix");
    constexpr int AOFF = 0, ALOFF = BM * SA, WOFF = 2 * BM * SA,
                  WLOFF = 2 * BM * SA + BN * SA;
    constexpr int STG = (2 * BM + 2 * BN) * SA;

    extern __shared__ __nv_bfloat16 smem[];
    uint32_t sbase;
    asm("{ .reg .u64 t; cvta.to.shared.u64 t, %1; cvt.u32.u64 %0, t; }"
        : "=r"(sbase) : "l"(smem));

    const int tid = threadIdx.x, lane = tid & 31, wid = tid >> 5;
    const int warpM = wid % WM, warpN = wid / WM;
    const int m0 = blockIdx.y * BM, n0 = blockIdx.x * BN;
    const int g = lane >> 2, c2 = (lane & 3) * 2;
    const int mbase = warpM * WTM, nbase = warpN * WTN;

    // ldmatrix per-lane row/col offsets
    const int a_row = (lane & 7) | (((lane >> 3) & 1) << 3);
    const int a_kof = ((lane >> 4) & 1) * 8;
    const int b_row = (lane & 7) | (((lane >> 4) & 1) << 3);
    const int b_kof = ((lane >> 3) & 1) * 8;

    float acc[MF][NF][4];
    #pragma unroll
    for (int mi = 0; mi < MF; mi++)
        #pragma unroll
        for (int ni = 0; ni < NF; ni++)
            #pragma unroll
            for (int q = 0; q < 4; q++) acc[mi][ni][q] = 0.f;

    const int NC = K / BK;

    auto load_chunk = [&](int c, int s) {
        const int kc = c * BK;
        const uint32_t st = sbase + (uint32_t)s * STG * 2;
        #pragma unroll
        for (int it = 0; it < (BM * 4 + 255) / 256; it++) {
            int i = tid + it * 256;
            if ((BM * 4) % 256 == 0 || i < BM * 4) {
                int r = i >> 2, q = i & 3;
                uint32_t d = st + (uint32_t)r * 80 + q * 16;
                const size_t go = (size_t)(m0 + r) * lda + kc + q * 8;
                cp16(d + AOFF * 2,  Ah + go);
                cp16(d + ALOFF * 2, Al + go);
            }
        }
        #pragma unroll
        for (int it = 0; it < (BN * 4 + 255) / 256; it++) {
            int i = tid + it * 256;
            if ((BN * 4) % 256 == 0 || i < BN * 4) {
                int r = i >> 2, q = i & 3;
                uint32_t d = st + (uint32_t)r * 80 + q * 16;
                const size_t go = (size_t)(n0 + r) * ldb + kc + q * 8;
                cp16(d + WOFF * 2,  Wh + go);
                cp16(d + WLOFF * 2, Wl + go);
            }
        }
    };

    load_chunk(0, 0);
    cp_commit();

    for (int c = 0; c < NC; c++) {
        const int s = c & 1;
        if (c + 1 < NC) {
            load_chunk(c + 1, (c + 1) & 1);
            cp_commit();
            cp_wait<1>();
        } else {
            cp_wait<0>();
        }
        __syncthreads();

        const uint32_t sb  = sbase + (uint32_t)s * STG * 2;
        const uint32_t pAh = sb + AOFF * 2,  pAl = sb + ALOFF * 2;
        const uint32_t pWh = sb + WOFF * 2,  pWl = sb + WLOFF * 2;

        #pragma unroll
        for (int ks = 0; ks < BK; ks += 16) {
            uint32_t ah[MF][4], al[MF][4], bh[NF][2], bl[NF][2];
            #pragma unroll
            for (int mi = 0; mi < MF; mi++)
                ldsm4(ah[mi], pAh + ((uint32_t)(mbase + mi * 16 + a_row) * SA
                                     + ks + a_kof) * 2);
            #pragma unroll
            for (int ni = 0; ni < NF; ni += 2) {
                uint32_t t[4];
                ldsm4(t, pWh + ((uint32_t)(nbase + ni * 8 + b_row) * SA
                                + ks + b_kof) * 2);
                bh[ni][0] = t[0]; bh[ni][1] = t[1];
                bh[ni + 1][0] = t[2]; bh[ni + 1][1] = t[3];
            }
            #pragma unroll
            for (int mi = 0; mi < MF; mi++)
                #pragma unroll
                for (int ni = 0; ni < NF; ni++)
                    mma16816(acc[mi][ni], ah[mi], bh[ni]);
            #pragma unroll
            for (int ni = 0; ni < NF; ni += 2) {
                uint32_t t[4];
                ldsm4(t, pWl + ((uint32_t)(nbase + ni * 8 + b_row) * SA
                                + ks + b_kof) * 2);
                bl[ni][0] = t[0]; bl[ni][1] = t[1];
                bl[ni + 1][0] = t[2]; bl[ni + 1][1] = t[3];
            }
            #pragma unroll
            for (int mi = 0; mi < MF; mi++)
                #pragma unroll
                for (int ni = 0; ni < NF; ni++)
                    mma16816(acc[mi][ni], ah[mi], bl[ni]);
            #pragma unroll
            for (int mi = 0; mi < MF; mi++)
                ldsm4(al[mi], pAl + ((uint32_t)(mbase + mi * 16 + a_row) * SA
                                     + ks + a_kof) * 2);
            #pragma unroll
            for (int mi = 0; mi < MF; mi++)
                #pragma unroll
                for (int ni = 0; ni < NF; ni++)
                    mma16816(acc[mi][ni], al[mi], bh[ni]);
        }
        __syncthreads();
    }

    #pragma unroll
    for (int mi = 0; mi < MF; mi++) {
        int row = m0 + mbase + mi * 16 + g;
        #pragma unroll
        for (int ni = 0; ni < NF; ni++) {
            int col = n0 + nbase + ni * 8 + c2;
            size_t o0 = (size_t)row * N + col;
            size_t o8 = (size_t)(row + 8) * N + col;
            *(float2*)(C + o0) = make_float2(acc[mi][ni][0], acc[mi][ni][1]);
            *(float2*)(C + o8) = make_float2(acc[mi][ni][2], acc[mi][ni][3]);
            if (WSPLIT) {
                uint32_t hw, lw;
                pack2(acc[mi][ni][0], acc[mi][ni][1], hw, lw);
                *(uint32_t*)(Chi + o0) = hw;
                *(uint32_t*)(Clo + o0) = lw;
                pack2(acc[mi][ni][2], acc[mi][ni][3], hw, lw);
                *(uint32_t*)(Chi + o8) = hw;
                *(uint32_t*)(Clo + o8) = lw;
            }
        }
    }
}

// ---------------- stage 1: per-pathway linear + LN -> bf16 hi/lo -------------
__global__ void __launch_bounds__(512) seg_ln_kernel(
    const float* __restrict__ series, const float* __restrict__ seg_w,
    const float* __restrict__ seg_b,  const float* __restrict__ ln_g,
    const float* __restrict__ ln_b)
{
    const int n  = blockIdx.x;
    const int b0 = blockIdx.y * 4;
    const int d  = threadIdx.x;
    __shared__ float s_s[4][PLEN];
    __shared__ float s_red[512];

    {
        int r = d >> 7, p = d & 127;
        s_s[r][p] = series[(size_t)(b0 + r) * (NPATH*PLEN) + n * PLEN + p];
    }
    __syncthreads();

    float sb = seg_b[n*DIMV + d];
    float acc0 = sb, acc1 = sb, acc2 = sb, acc3 = sb;
    const float* wp = seg_w + (size_t)n * PLEN * DIMV + d;
    #pragma unroll 4
    for (int p = 0; p < PLEN; p++) {
        float w = wp[(size_t)p * DIMV];
        acc0 += s_s[0][p] * w;
        acc1 += s_s[1][p] * w;
        acc2 += s_s[2][p] * w;
        acc3 += s_s[3][p] * w;
    }
    float gam = ln_g[n*DIMV + d], bet = ln_b[n*DIMV + d];
    float accs[4] = {acc0, acc1, acc2, acc3};
    #pragma unroll
    for (int r = 0; r < 4; r++) {
        float v = accs[r];
        s_red[d] = v; __syncthreads();
        for (int s = 256; s > 0; s >>= 1) {
            if (d < s) s_red[d] += s_red[d + s];
            __syncthreads();
        }
        float mu = s_red[0] * (1.0f / DIMV);
        __syncthreads();
        float c = v - mu;
        s_red[d] = c * c; __syncthreads();
        for (int s = 256; s > 0; s >>= 1) {
            if (d < s) s_red[d] += s_red[d + s];
            __syncthreads();
        }
        float var = s_red[0] * (1.0f / DIMV);
        __syncthreads();
        float rstd = rsqrtf(var + 1e-5f);
        float o = c * rstd * gam + bet;
        size_t idx = ((size_t)(b0 + r) * NPATH + n) * DIMV + d;
        __nv_bfloat16 h = __float2bfloat16_rn(o);
        g_ah[idx] = h;
        g_al[idx] = __float2bfloat16_rn(o - __bfloat162float(h));
    }
}

// ---------------- FFMA GEMM (kept for the tiny dt_proj) ----------------------
template<int BM, int BN, int TM, int TN, int EPI>
__global__ void __launch_bounds__(256) gemm_nt(
    const float* __restrict__ A, const float* __restrict__ Bw,
    const float* __restrict__ bias, float* __restrict__ C,
    int M, int N, int K, int lda)
{
    constexpr int BK = 16;
    __shared__ float As[BK][BM];
    __shared__ float Bs[BK][BN];
    const int tid = threadIdx.x;
    const int m0 = blockIdx.y * BM;
    const int n0 = blockIdx.x * BN;
    constexpr int NTX = BN / TN;
    static_assert((BM / TM) * (BN / TN) == 256, "thread tiling");
    const int tx = tid % NTX;
    const int ty = tid / NTX;

    float acc[TM][TN];
    #pragma unroll
    for (int i = 0; i < TM; i++)
        #pragma unroll
        for (int j = 0; j < TN; j++) acc[i][j] = 0.f;

    constexpr int A_F4 = BM * 4;
    constexpr int B_F4 = BN * 4;

    for (int k0 = 0; k0 < K; k0 += BK) {
        #pragma unroll
        for (int l = 0; l < (A_F4 + 255) / 256; l++) {
            int idx = tid + l * 256;
            if ((A_F4 % 256) == 0 || idx < A_F4) {
                int row = idx >> 2, kq = (idx & 3) << 2;
                float4 v = *(const float4*)(A + (size_t)(m0 + row) * lda + k0 + kq);
                As[kq + 0][row] = v.x; As[kq + 1][row] = v.y;
                As[kq + 2][row] = v.z; As[kq + 3][row] = v.w;
            }
        }
        #pragma unroll
        for (int l = 0; l < (B_F4 + 255) / 256; l++) {
            int idx = tid + l * 256;
            if ((B_F4 % 256) == 0 || idx < B_F4) {
                int row = idx >> 2, kq = (idx & 3) << 2;
                float4 v = *(const float4*)(Bw + (size_t)(n0 + row) * K + k0 + kq);
                Bs[kq + 0][row] = v.x; Bs[kq + 1][row] = v.y;
                Bs[kq + 2][row] = v.z; Bs[kq + 3][row] = v.w;
            }
        }
        __syncthreads();
        #pragma unroll
        for (int kk = 0; kk < BK; kk++) {
            float a[TM], bfr[TN];
            #pragma unroll
            for (int i = 0; i < TM; i++) a[i] = As[kk][ty * TM + i];
            #pragma unroll
            for (int j = 0; j < TN; j++) bfr[j] = Bs[kk][tx * TN + j];
            #pragma unroll
            for (int i = 0; i < TM; i++)
                #pragma unroll
                for (int j = 0; j < TN; j++) acc[i][j] += a[i] * bfr[j];
        }
        __syncthreads();
    }

    #pragma unroll
    for (int i = 0; i < TM; i++) {
        int m = m0 + ty * TM + i;
        #pragma unroll
        for (int j = 0; j < TN; j++) {
            int n = n0 + tx * TN + j;
            float v = acc[i][j];
            if (EPI == 1) v = softplusf(v + bias[n]);
            C[(size_t)m * N + n] = v;
        }
    }
}

// ---------------- conv (k=4) + bias + silu -> fp32 uc + bf16 hi/lo -----------
__global__ void __launch_bounds__(256) conv_silu_kernel(
    const float* __restrict__ cw, const float* __restrict__ cb)
{
    int idx = blockIdx.x * blockDim.x + threadIdx.x;
    int c4  = (idx & (DINV/4 - 1)) << 2;
    int row = idx >> 8;
    int t   = row & (SEQ - 1);
    const float* urow = g_xz + (size_t)row * XZW + c4;

    float4 w0 = *(const float4*)(cw + (size_t)(c4 + 0) * 4);
    float4 w1 = *(const float4*)(cw + (size_t)(c4 + 1) * 4);
    float4 w2 = *(const float4*)(cw + (size_t)(c4 + 2) * 4);
    float4 w3 = *(const float4*)(cw + (size_t)(c4 + 3) * 4);
    float4 a  = *(const float4*)(cb + c4);

    if (t - 3 >= 0) {
        float4 u = *(const float4*)(urow - (size_t)3 * XZW);
        a.x += u.x * w0.x; a.y += u.y * w1.x; a.z += u.z * w2.x; a.w += u.w * w3.x;
    }
    if (t - 2 >= 0) {
        float4 u = *(const float4*)(urow - (size_t)2 * XZW);
        a.x += u.x * w0.y; a.y += u.y * w1.y; a.z += u.z * w2.y; a.w += u.w * w3.y;
    }
    if (t - 1 >= 0) {
        float4 u = *(const float4*)(urow - (size_t)1 * XZW);
        a.x += u.x * w0.z; a.y += u.y * w1.z; a.z += u.z * w2.z; a.w += u.w * w3.z;
    }
    {
        float4 u = *(const float4*)(urow);
        a.x += u.x * w0.w; a.y += u.y * w1.w; a.z += u.z * w2.w; a.w += u.w * w3.w;
    }
    a.x = a.x / (1.0f + __expf(-a.x));
    a.y = a.y / (1.0f + __expf(-a.y));
    a.z = a.z / (1.0f + __expf(-a.z));
    a.w = a.w / (1.0f + __expf(-a.w));
    size_t o = (size_t)row * DINV + c4;
    *(float4*)(g_uc + o) = a;
    uint2 hw, lw; cvt_hl(a, hw, lw);
    *(uint2*)(g_ah + o) = hw;
    *(uint2*)(g_al + o) = lw;
}

// ---------------- selective scan + gate -> bf16 hi/lo y -----------------------
__global__ void __launch_bounds__(256) scan_kernel(
    const float* __restrict__ A_log, const float* __restrict__ Dp_)
{
    const int b = blockIdx.x;
    const int d = blockIdx.y * 256 + threadIdx.x;
    __shared__ float sB[SEQ][NSTATE];
    __shared__ float sC[SEQ][NSTATE];

    for (int i = threadIdx.x; i < SEQ * 2 * NSTATE; i += 256) {
        int t = i >> 5, j = i & 31;
        float v = g_xdbl[((size_t)(b * SEQ + t)) * 64 + 32 + j];
        if (j < 16) sB[t][j] = v; else sC[t][j - 16] = v;
    }
    __syncthreads();

    float rA[NSTATE];
    #pragma unroll
    for (int n = 0; n < NSTATE; n++) rA[n] = -expf(A_log[(size_t)d * NSTATE + n]);
    const float Dv = Dp_[d];
    float h[NSTATE];
    #pragma unroll
    for (int n = 0; n < NSTATE; n++) h[n] = 0.f;

    const size_t rowbase = (size_t)b * SEQ;
    for (int t = 0; t < SEQ; t++) {
        const size_t row = rowbase + t;
        float delta = g_delta[row * DINV + d];
        float u     = g_uc[row * DINV + d];
        float du    = delta * u;
        float y = 0.f;
        #pragma unroll
        for (int n = 0; n < NSTATE; n++) {
            float dA = __expf(delta * rA[n]);
            h[n] = dA * h[n] + du * sB[t][n];
            y += h[n] * sC[t][n];
        }
        float z = g_xz[row * XZW + DINV + d];
        float silu_z = z / (1.0f + __expf(-z));
        float yv = (y + u * Dv) * silu_z;
        __nv_bfloat16 hb = __float2bfloat16_rn(yv);
        g_bh[row * DINV + d] = hb;
        g_bl[row * DINV + d] = __float2bfloat16_rn(yv - __bfloat162float(hb));
    }
}

// ---------------- final LayerNorm stats ---------------------------------------
__global__ void __launch_bounds__(256) ln_stats_kernel()
{
    const int b = blockIdx.x;
    const float4* xp = (const float4*)(g_x + (size_t)b * HEADK);
    float s = 0.f, sq = 0.f;
    for (int i = threadIdx.x; i < HEADK / 4; i += 256) {
        float4 v = xp[i];
        s  += v.x + v.y + v.z + v.w;
        sq += v.x*v.x + v.y*v.y + v.z*v.z + v.w*v.w;
    }
    __shared__ float rs[256], rq[256];
    rs[threadIdx.x] = s; rq[threadIdx.x] = sq; __syncthreads();
    for (int st = 128; st > 0; st >>= 1) {
        if (threadIdx.x < st) { rs[threadIdx.x] += rs[threadIdx.x + st];
                                rq[threadIdx.x] += rq[threadIdx.x + st]; }
        __syncthreads();
    }
    if (threadIdx.x == 0) {
        float mu  = rs[0] / (float)HEADK;
        float var = rq[0] / (float)HEADK - mu * mu;
        g_stats[b] = make_float2(mu, rsqrtf(var + 1e-5f));
    }
}

// ---------------- head: split-K GEMM (LN fused on A load) --------------------
__global__ void __launch_bounds__(256) head_gemm_kernel(
    const float* __restrict__ lng, const float* __restrict__ lnb,
    const float* __restrict__ hw)
{
    constexpr int BK = 16;
    const int slab = blockIdx.x;
    const int kbeg = slab * (HEADK / HSLABS);
    __shared__ float sX[BK][BATCH];
    __shared__ float sW[BK][NCLS];
    const int tid = threadIdx.x;
    const int tx = tid & 15;
    const int ty = tid >> 4;

    float acc[8][2];
    #pragma unroll
    for (int i = 0; i < 8; i++) { acc[i][0] = 0.f; acc[i][1] = 0.f; }

    for (int k0 = kbeg; k0 < kbeg + HEADK / HSLABS; k0 += BK) {
        #pragma unroll
        for (int l = 0; l < 2; l++) {
            int idx = tid + l * 256;
            int row = idx >> 2, kq = (idx & 3) << 2;
            float2 st = g_stats[row];
            float4 v  = *(const float4*)(g_x + (size_t)row * HEADK + k0 + kq);
            float4 gg = *(const float4*)(lng + k0 + kq);
            float4 bb = *(const float4*)(lnb + k0 + kq);
            sX[kq + 0][row] = (v.x - st.x) * st.y * gg.x + bb.x;
            sX[kq + 1][row] = (v.y - st.x) * st.y * gg.y + bb.y;
            sX[kq + 2][row] = (v.z - st.x) * st.y * gg.z + bb.z;
            sX[kq + 3][row] = (v.w - st.x) * st.y * gg.w + bb.w;
        }
        if (tid < 128) {
            int row = tid >> 2, kq = (tid & 3) << 2;
            float4 v = *(const float4*)(hw + (size_t)row * HEADK + k0 + kq);
            sW[kq + 0][row] = v.x; sW[kq + 1][row] = v.y;
            sW[kq + 2][row] = v.z; sW[kq + 3][row] = v.w;
        }
        __syncthreads();
        #pragma unroll
        for (int kk = 0; kk < BK; kk++) {
            float w0 = sW[kk][tx * 2], w1 = sW[kk][tx * 2 + 1];
            #pragma unroll
            for (int i = 0; i < 8; i++) {
                float a = sX[kk][ty * 8 + i];
                acc[i][0] += a * w0;
                acc[i][1] += a * w1;
            }
        }
        __syncthreads();
    }
    #pragma unroll
    for (int i = 0; i < 8; i++) {
        int m = ty * 8 + i;
        g_hpart[((size_t)slab * BATCH + m) * NCLS + tx * 2 + 0] = acc[i][0];
        g_hpart[((size_t)slab * BATCH + m) * NCLS + tx * 2 + 1] = acc[i][1];
    }
}

__global__ void __launch_bounds__(256) head_reduce_kernel(
    const float* __restrict__ head_b, float* __restrict__ out)
{
    int idx = blockIdx.x * blockDim.x + threadIdx.x;
    if (idx < BATCH * NCLS) {
        float s = head_b[idx & (NCLS - 1)];
        for (int sl = 0; sl < HSLABS; sl++)
            s += g_hpart[(size_t)sl * BATCH * NCLS + idx];
        out[idx] = s;
    }
}

// ---------------- host orchestration -----------------------------------------
extern "C" void kernel_launch(void* const* d_in, const int* in_sizes, int n_in,
                              void* d_out, int out_size)
{
    const float* series    = (const float*)d_in[0];
    const float* seg_w     = (const float*)d_in[1];
    const float* seg_b     = (const float*)d_in[2];
    const float* ln_g      = (const float*)d_in[3];
    const float* ln_b      = (const float*)d_in[4];
    const float* in_proj_w = (const float*)d_in[5];
    const float* conv_w    = (const float*)d_in[6];
    const float* conv_b    = (const float*)d_in[7];
    const float* x_proj_w  = (const float*)d_in[8];
    const float* dt_proj_w = (const float*)d_in[9];
    const float* dt_proj_b = (const float*)d_in[10];
    const float* A_log     = (const float*)d_in[11];
    const float* Dw        = (const float*)d_in[12];
    const float* out_proj_w= (const float*)d_in[13];
    const float* hlng      = (const float*)d_in[14];
    const float* hlnb      = (const float*)d_in[15];
    const float* head_w    = (const float*)d_in[16];
    const float* head_b    = (const float*)d_in[17];
    float* out = (float*)d_out;

    float *px, *pxz, *puc, *pxdbl, *pdelta;
    __nv_bfloat16 *pah, *pal, *pbh, *pbl, *pwh, *pwl;
    cudaGetSymbolAddress((void**)&px,     g_x);
    cudaGetSymbolAddress((void**)&pxz,    g_xz);
    cudaGetSymbolAddress((void**)&puc,    g_uc);
    cudaGetSymbolAddress((void**)&pxdbl,  g_xdbl);
    cudaGetSymbolAddress((void**)&pdelta, g_delta);
    cudaGetSymbolAddress((void**)&pah,    g_ah);
    cudaGetSymbolAddress((void**)&pal,    g_al);
    cudaGetSymbolAddress((void**)&pbh,    g_bh);
    cudaGetSymbolAddress((void**)&pbl,    g_bl);
    cudaGetSymbolAddress((void**)&pwh,    g_wh);
    cudaGetSymbolAddress((void**)&pwl,    g_wl);

    const int SMEM128 = 2 * (2*128 + 2*128) * 40 * 2;  // 81920
    const int SMEM64  = 2 * (2*64  + 2*64 ) * 40 * 2;  // 40960
    cudaFuncSetAttribute((const void*)hmma_gemm<128,128,2,4,false>,
                         cudaFuncAttributeMaxDynamicSharedMemorySize, SMEM128);
    cudaFuncSetAttribute((const void*)hmma_gemm<128,128,2,4,true>,
                         cudaFuncAttributeMaxDynamicSharedMemorySize, SMEM128);
    cudaFuncSetAttribute((const void*)hmma_gemm<64,64,2,4,false>,
                         cudaFuncAttributeMaxDynamicSharedMemorySize, SMEM64);

    auto split = [](const float* src, __nv_bfloat16* hi, __nv_bfloat16* lo, int n) {
        split_kernel<<<(n/4 + 255)/256, 256>>>(src, hi, lo, n/4);
    };

    // 1) segment linear + LN -> bf16 hi/lo pair A
    seg_ln_kernel<<<dim3(NPATH, BATCH/4), 512>>>(series, seg_w, seg_b, ln_g, ln_b);

    for (int dep = 0; dep < DEPTHN; dep++) {
        // 2) in_proj: [8192,512]x[4096,512]^T -> g_xz (fp32)
        split(in_proj_w + (size_t)dep * XZW * DIMV, pwh, pwl, XZW * DIMV);
        hmma_gemm<128,128,2,4,false><<<dim3(XZW/128, ROWSZ/128), 256, SMEM128>>>(
            pah, pal, pwh, pwl, pxz, nullptr, nullptr,
            ROWSZ, XZW, DIMV, DIMV, DIMV);
        // 3) conv + silu -> g_uc fp32 + pair A hi/lo
        conv_silu_kernel<<<(ROWSZ * (DINV/4)) / 256, 256>>>(
            conv_w + (size_t)dep * DINV * 4, conv_b + (size_t)dep * DINV);
        // 4) x_proj: [8192,1024]x[64,1024]^T -> g_xdbl
        split(x_proj_w + (size_t)dep * 64 * DINV, pwh, pwl, 64 * DINV);
        hmma_gemm<64,64,2,4,false><<<dim3(1, ROWSZ/64), 256, SMEM64>>>(
            pah, pal, pwh, pwl, pxdbl, nullptr, nullptr,
            ROWSZ, 64, DINV, DINV, DINV);
        // 5) dt_proj + bias + softplus (FFMA; K=32)
        gemm_nt<128,64,8,4,1><<<dim3(DINV/64, ROWSZ/128), 256>>>(
            pxdbl, dt_proj_w + (size_t)dep * DINV * DTRV,
            dt_proj_b + (size_t)dep * DINV, pdelta,
            ROWSZ, DINV, DTRV, 64);
        // 6) scan + D skip + silu(z) gate -> pair B hi/lo
        scan_kernel<<<dim3(BATCH, DINV/256), 256>>>(
            A_log + (size_t)dep * DINV * NSTATE, Dw + (size_t)dep * DINV);
        // 7) out_proj: [8192,1024]x[512,1024]^T -> g_x fp32 + pair A hi/lo
        split(out_proj_w + (size_t)dep * DIMV * DINV, pwh, pwl, DIMV * DINV);
        hmma_gemm<128,128,2,4,true><<<dim3(DIMV/128, ROWSZ/128), 256, SMEM128>>>(
            pbh, pbl, pwh, pwl, px, pah, pal,
            ROWSZ, DIMV, DINV, DINV, DINV);
    }

    // 8) final LN stats + head GEMM + deterministic reduce
    ln_stats_kernel<<<BATCH, 256>>>();
    head_gemm_kernel<<<HSLABS, 256>>>(hlng, hlnb, head_w);
    head_reduce_kernel<<<(BATCH*NCLS + 255)/256, 256>>>(head_b, out);
}

// round 6
// speedup vs baseline: 2.1621x; 1.0359x over previous
#include <cuda_runtime.h>
#include <cuda_bf16.h>
#include <math.h>
#include <stdint.h>

// Problem constants
#define BATCH   128
#define NPATH   64
#define PLEN    128
#define DIMV    512
#define NSTATE  16
#define DEPTHN  2
#define DINV    1024
#define DTRV    32
#define NCLS    32
#define SEQ     64
#define ROWSZ   (BATCH*SEQ)        // 8192
#define XZW     (2*DINV)           // 4096
#define HEADK   (NPATH*DIMV)       // 32768
#define HSLABS  64

// ---------------- scratch (static device globals; no allocation) -------------
__device__ float  g_x[(size_t)ROWSZ*DIMV];
__device__ float  g_xz[(size_t)ROWSZ*XZW];
__device__ float  g_xdbl[(size_t)ROWSZ*64];
__device__ float2 g_stats[BATCH];
__device__ float  g_hpart[(size_t)HSLABS*BATCH*NCLS];
// bf16 hi/lo split buffers: pair A (x / uc), pair B (scan y)
__device__ __nv_bfloat16 g_ah[(size_t)ROWSZ*DINV];
__device__ __nv_bfloat16 g_al[(size_t)ROWSZ*DINV];
__device__ __nv_bfloat16 g_bh[(size_t)ROWSZ*DINV];
__device__ __nv_bfloat16 g_bl[(size_t)ROWSZ*DINV];
__device__ __nv_bfloat16 g_wh[(size_t)XZW*DIMV];
__device__ __nv_bfloat16 g_wl[(size_t)XZW*DIMV];

__device__ __forceinline__ float softplusf(float x) {
    return fmaxf(x, 0.0f) + log1pf(expf(-fabsf(x)));
}

__device__ __forceinline__ void cvt_hl(float4 v, uint2& hw, uint2& lw) {
    float f[4] = {v.x, v.y, v.z, v.w};
    unsigned short h[4], l[4];
    #pragma unroll
    for (int i = 0; i < 4; i++) {
        __nv_bfloat16 hb = __float2bfloat16_rn(f[i]);
        h[i] = __bfloat16_as_ushort(hb);
        float r = f[i] - __bfloat162float(hb);
        l[i] = __bfloat16_as_ushort(__float2bfloat16_rn(r));
    }
    hw.x = (uint32_t)h[0] | ((uint32_t)h[1] << 16);
    hw.y = (uint32_t)h[2] | ((uint32_t)h[3] << 16);
    lw.x = (uint32_t)l[0] | ((uint32_t)l[1] << 16);
    lw.y = (uint32_t)l[2] | ((uint32_t)l[3] << 16);
}

__device__ __forceinline__ void pack2(float v0, float v1, uint32_t& hw, uint32_t& lw) {
    __nv_bfloat16 h0 = __float2bfloat16_rn(v0);
    __nv_bfloat16 h1 = __float2bfloat16_rn(v1);
    float r0 = v0 - __bfloat162float(h0), r1 = v1 - __bfloat162float(h1);
    hw = (uint32_t)__bfloat16_as_ushort(h0) | ((uint32_t)__bfloat16_as_ushort(h1) << 16);
    lw = (uint32_t)__bfloat16_as_ushort(__float2bfloat16_rn(r0))
       | ((uint32_t)__bfloat16_as_ushort(__float2bfloat16_rn(r1)) << 16);
}

__global__ void __launch_bounds__(256) split_kernel(
    const float* __restrict__ src, __nv_bfloat16* __restrict__ hi,
    __nv_bfloat16* __restrict__ lo, int n4)
{
    int i = blockIdx.x * blockDim.x + threadIdx.x;
    if (i < n4) {
        float4 v = ((const float4*)src)[i];
        uint2 hw, lw; cvt_hl(v, hw, lw);
        ((uint2*)hi)[i] = hw;
        ((uint2*)lo)[i] = lw;
    }
}

__device__ __forceinline__ void mma16816(float* c, const uint32_t* a, const uint32_t* b) {
    asm volatile(
        "mma.sync.aligned.m16n8k16.row.col.f32.bf16.bf16.f32 "
        "{%0,%1,%2,%3}, {%4,%5,%6,%7}, {%8,%9}, {%0,%1,%2,%3};"
        : "+f"(c[0]), "+f"(c[1]), "+f"(c[2]), "+f"(c[3])
        : "r"(a[0]), "r"(a[1]), "r"(a[2]), "r"(a[3]), "r"(b[0]), "r"(b[1]));
}
__device__ __forceinline__ void ldsm4(uint32_t* r, uint32_t addr) {
    asm volatile("ldmatrix.sync.aligned.m8n8.x4.shared.b16 {%0,%1,%2,%3}, [%4];"
        : "=r"(r[0]), "=r"(r[1]), "=r"(r[2]), "=r"(r[3]) : "r"(addr));
}
__device__ __forceinline__ void cp16(uint32_t dst, const void* src) {
    asm volatile("cp.async.cg.shared.global [%0], [%1], 16;" :: "r"(dst), "l"(src));
}
__device__ __forceinline__ void cp_commit() {
    asm volatile("cp.async.commit_group;" ::: "memory");
}
template<int N>
__device__ __forceinline__ void cp_wait() {
    asm volatile("cp.async.wait_group %0;" :: "n"(N) : "memory");
}

// =============== HMMA bf16x3 GEMM (ldmatrix + cp.async pipeline) =============
template<int BM, int BN, int WM, int WN, bool WSPLIT>
__global__ void __launch_bounds__(256, 2) hmma_gemm(
    const __nv_bfloat16* __restrict__ Ah, const __nv_bfloat16* __restrict__ Al,
    const __nv_bfloat16* __restrict__ Wh, const __nv_bfloat16* __restrict__ Wl,
    float* __restrict__ C, __nv_bfloat16* __restrict__ Chi,
    __nv_bfloat16* __restrict__ Clo, int M, int N, int K, int lda, int ldb)
{
    constexpr int BK = 32, SA = 40;
    constexpr int WTM = BM / WM, WTN = BN / WN;
    constexpr int MF = WTM / 16, NF = WTN / 8;
    static_assert(WM * WN == 8, "8 warps");
    static_assert(NF % 2 == 0, "NF even for paired ldmatrix");
    constexpr int AOFF = 0, ALOFF = BM * SA, WOFF = 2 * BM * SA,
                  WLOFF = 2 * BM * SA + BN * SA;
    constexpr int STG = (2 * BM + 2 * BN) * SA;

    extern __shared__ __nv_bfloat16 smem[];
    uint32_t sbase;
    asm("{ .reg .u64 t; cvta.to.shared.u64 t, %1; cvt.u32.u64 %0, t; }"
        : "=r"(sbase) : "l"(smem));

    const int tid = threadIdx.x, lane = tid & 31, wid = tid >> 5;
    const int warpM = wid % WM, warpN = wid / WM;
    const int m0 = blockIdx.y * BM, n0 = blockIdx.x * BN;
    const int g = lane >> 2, c2 = (lane & 3) * 2;
    const int mbase = warpM * WTM, nbase = warpN * WTN;

    const int a_row = (lane & 7) | (((lane >> 3) & 1) << 3);
    const int a_kof = ((lane >> 4) & 1) * 8;
    const int b_row = (lane & 7) | (((lane >> 4) & 1) << 3);
    const int b_kof = ((lane >> 3) & 1) * 8;

    float acc[MF][NF][4];
    #pragma unroll
    for (int mi = 0; mi < MF; mi++)
        #pragma unroll
        for (int ni = 0; ni < NF; ni++)
            #pragma unroll
            for (int q = 0; q < 4; q++) acc[mi][ni][q] = 0.f;

    const int NC = K / BK;

    auto load_chunk = [&](int c, int s) {
        const int kc = c * BK;
        const uint32_t st = sbase + (uint32_t)s * STG * 2;
        #pragma unroll
        for (int it = 0; it < (BM * 4 + 255) / 256; it++) {
            int i = tid + it * 256;
            if ((BM * 4) % 256 == 0 || i < BM * 4) {
                int r = i >> 2, q = i & 3;
                uint32_t d = st + (uint32_t)r * 80 + q * 16;
                const size_t go = (size_t)(m0 + r) * lda + kc + q * 8;
                cp16(d + AOFF * 2,  Ah + go);
                cp16(d + ALOFF * 2, Al + go);
            }
        }
        #pragma unroll
        for (int it = 0; it < (BN * 4 + 255) / 256; it++) {
            int i = tid + it * 256;
            if ((BN * 4) % 256 == 0 || i < BN * 4) {
                int r = i >> 2, q = i & 3;
                uint32_t d = st + (uint32_t)r * 80 + q * 16;
                const size_t go = (size_t)(n0 + r) * ldb + kc + q * 8;
                cp16(d + WOFF * 2,  Wh + go);
                cp16(d + WLOFF * 2, Wl + go);
            }
        }
    };

    load_chunk(0, 0);
    cp_commit();

    for (int c = 0; c < NC; c++) {
        const int s = c & 1;
        if (c + 1 < NC) {
            load_chunk(c + 1, (c + 1) & 1);
            cp_commit();
            cp_wait<1>();
        } else {
            cp_wait<0>();
        }
        __syncthreads();

        const uint32_t sb  = sbase + (uint32_t)s * STG * 2;
        const uint32_t pAh = sb + AOFF * 2,  pAl = sb + ALOFF * 2;
        const uint32_t pWh = sb + WOFF * 2,  pWl = sb + WLOFF * 2;

        #pragma unroll
        for (int ks = 0; ks < BK; ks += 16) {
            uint32_t ah[MF][4], al[MF][4], bh[NF][2], bl[NF][2];
            #pragma unroll
            for (int mi = 0; mi < MF; mi++)
                ldsm4(ah[mi], pAh + ((uint32_t)(mbase + mi * 16 + a_row) * SA
                                     + ks + a_kof) * 2);
            #pragma unroll
            for (int ni = 0; ni < NF; ni += 2) {
                uint32_t t[4];
                ldsm4(t, pWh + ((uint32_t)(nbase + ni * 8 + b_row) * SA
                                + ks + b_kof) * 2);
                bh[ni][0] = t[0]; bh[ni][1] = t[1];
                bh[ni + 1][0] = t[2]; bh[ni + 1][1] = t[3];
            }
            #pragma unroll
            for (int mi = 0; mi < MF; mi++)
                #pragma unroll
                for (int ni = 0; ni < NF; ni++)
                    mma16816(acc[mi][ni], ah[mi], bh[ni]);
            #pragma unroll
            for (int ni = 0; ni < NF; ni += 2) {
                uint32_t t[4];
                ldsm4(t, pWl + ((uint32_t)(nbase + ni * 8 + b_row) * SA
                                + ks + b_kof) * 2);
                bl[ni][0] = t[0]; bl[ni][1] = t[1];
                bl[ni + 1][0] = t[2]; bl[ni + 1][1] = t[3];
            }
            #pragma unroll
            for (int mi = 0; mi < MF; mi++)
                #pragma unroll
                for (int ni = 0; ni < NF; ni++)
                    mma16816(acc[mi][ni], ah[mi], bl[ni]);
            #pragma unroll
            for (int mi = 0; mi < MF; mi++)
                ldsm4(al[mi], pAl + ((uint32_t)(mbase + mi * 16 + a_row) * SA
                                     + ks + a_kof) * 2);
            #pragma unroll
            for (int mi = 0; mi < MF; mi++)
                #pragma unroll
                for (int ni = 0; ni < NF; ni++)
                    mma16816(acc[mi][ni], al[mi], bh[ni]);
        }
        __syncthreads();
    }

    #pragma unroll
    for (int mi = 0; mi < MF; mi++) {
        int row = m0 + mbase + mi * 16 + g;
        #pragma unroll
        for (int ni = 0; ni < NF; ni++) {
            int col = n0 + nbase + ni * 8 + c2;
            size_t o0 = (size_t)row * N + col;
            size_t o8 = (size_t)(row + 8) * N + col;
            *(float2*)(C + o0) = make_float2(acc[mi][ni][0], acc[mi][ni][1]);
            *(float2*)(C + o8) = make_float2(acc[mi][ni][2], acc[mi][ni][3]);
            if (WSPLIT) {
                uint32_t hw, lw;
                pack2(acc[mi][ni][0], acc[mi][ni][1], hw, lw);
                *(uint32_t*)(Chi + o0) = hw;
                *(uint32_t*)(Clo + o0) = lw;
                pack2(acc[mi][ni][2], acc[mi][ni][3], hw, lw);
                *(uint32_t*)(Chi + o8) = hw;
                *(uint32_t*)(Clo + o8) = lw;
            }
        }
    }
}

// ---------------- stage 1: per-pathway linear + LN -> bf16 hi/lo -------------
__global__ void __launch_bounds__(512) seg_ln_kernel(
    const float* __restrict__ series, const float* __restrict__ seg_w,
    const float* __restrict__ seg_b,  const float* __restrict__ ln_g,
    const float* __restrict__ ln_b)
{
    const int n  = blockIdx.x;
    const int b0 = blockIdx.y * 4;
    const int d  = threadIdx.x;
    __shared__ float s_s[4][PLEN];
    __shared__ float s_red[512];

    {
        int r = d >> 7, p = d & 127;
        s_s[r][p] = series[(size_t)(b0 + r) * (NPATH*PLEN) + n * PLEN + p];
    }
    __syncthreads();

    float sb = seg_b[n*DIMV + d];
    float acc0 = sb, acc1 = sb, acc2 = sb, acc3 = sb;
    const float* wp = seg_w + (size_t)n * PLEN * DIMV + d;
    #pragma unroll 4
    for (int p = 0; p < PLEN; p++) {
        float w = wp[(size_t)p * DIMV];
        acc0 += s_s[0][p] * w;
        acc1 += s_s[1][p] * w;
        acc2 += s_s[2][p] * w;
        acc3 += s_s[3][p] * w;
    }
    float gam = ln_g[n*DIMV + d], bet = ln_b[n*DIMV + d];
    float accs[4] = {acc0, acc1, acc2, acc3};
    #pragma unroll
    for (int r = 0; r < 4; r++) {
        float v = accs[r];
        s_red[d] = v; __syncthreads();
        for (int s = 256; s > 0; s >>= 1) {
            if (d < s) s_red[d] += s_red[d + s];
            __syncthreads();
        }
        float mu = s_red[0] * (1.0f / DIMV);
        __syncthreads();
        float c = v - mu;
        s_red[d] = c * c; __syncthreads();
        for (int s = 256; s > 0; s >>= 1) {
            if (d < s) s_red[d] += s_red[d + s];
            __syncthreads();
        }
        float var = s_red[0] * (1.0f / DIMV);
        __syncthreads();
        float rstd = rsqrtf(var + 1e-5f);
        float o = c * rstd * gam + bet;
        size_t idx = ((size_t)(b0 + r) * NPATH + n) * DIMV + d;
        __nv_bfloat16 h = __float2bfloat16_rn(o);
        g_ah[idx] = h;
        g_al[idx] = __float2bfloat16_rn(o - __bfloat162float(h));
    }
}

// ------- conv (k=4, t-marching) + bias + silu -> bf16 hi/lo pair A only ------
// grid (BATCH, SEQ/16); thread owns 4 channels, walks 16 timesteps.
__global__ void __launch_bounds__(256) conv_silu_kernel(
    const float* __restrict__ cw, const float* __restrict__ cb)
{
    const int b  = blockIdx.x;
    const int t0 = blockIdx.y * 16;
    const int c4 = threadIdx.x * 4;

    float4 w0 = *(const float4*)(cw + (size_t)(c4 + 0) * 4);
    float4 w1 = *(const float4*)(cw + (size_t)(c4 + 1) * 4);
    float4 w2 = *(const float4*)(cw + (size_t)(c4 + 2) * 4);
    float4 w3 = *(const float4*)(cw + (size_t)(c4 + 3) * 4);
    float4 bias = *(const float4*)(cb + c4);

    const float* ubase = g_xz + (size_t)b * SEQ * XZW + c4;
    float4 um3 = make_float4(0,0,0,0), um2 = um3, um1 = um3;
    if (t0 - 3 >= 0) um3 = *(const float4*)(ubase + (size_t)(t0 - 3) * XZW);
    if (t0 - 2 >= 0) um2 = *(const float4*)(ubase + (size_t)(t0 - 2) * XZW);
    if (t0 - 1 >= 0) um1 = *(const float4*)(ubase + (size_t)(t0 - 1) * XZW);

    #pragma unroll
    for (int tt = 0; tt < 16; tt++) {
        const int t = t0 + tt;
        float4 u = *(const float4*)(ubase + (size_t)t * XZW);
        float4 a;
        a.x = bias.x + um3.x*w0.x + um2.x*w0.y + um1.x*w0.z + u.x*w0.w;
        a.y = bias.y + um3.y*w1.x + um2.y*w1.y + um1.y*w1.z + u.y*w1.w;
        a.z = bias.z + um3.z*w2.x + um2.z*w2.y + um1.z*w2.z + u.z*w2.w;
        a.w = bias.w + um3.w*w3.x + um2.w*w3.y + um1.w*w3.z + u.w*w3.w;
        a.x = a.x / (1.0f + __expf(-a.x));
        a.y = a.y / (1.0f + __expf(-a.y));
        a.z = a.z / (1.0f + __expf(-a.z));
        a.w = a.w / (1.0f + __expf(-a.w));
        size_t o = ((size_t)b * SEQ + t) * DINV + c4;
        uint2 hw, lw; cvt_hl(a, hw, lw);
        *(uint2*)(g_ah + o) = hw;
        *(uint2*)(g_al + o) = lw;
        um3 = um2; um2 = um1; um1 = u;
    }
}

// -------- fused dt_proj + softplus + selective scan + gate -> pair B ---------
// grid (BATCH, DINV/256); thread owns (b, d), h[16] in regs, marches t.
__global__ void __launch_bounds__(256) scan_kernel(
    const float* __restrict__ A_log, const float* __restrict__ Dp_,
    const float* __restrict__ wdt,   const float* __restrict__ bdt)
{
    const int b = blockIdx.x;
    const int d = blockIdx.y * 256 + threadIdx.x;
    __shared__ float sB[SEQ][NSTATE];
    __shared__ float sC[SEQ][NSTATE];
    __shared__ float sDT[SEQ][DTRV];

    for (int i = threadIdx.x; i < SEQ * 64; i += 256) {
        int t = i >> 6, j = i & 63;
        float v = g_xdbl[((size_t)(b * SEQ + t)) * 64 + j];
        if (j < 32)       sDT[t][j] = v;
        else if (j < 48)  sB[t][j - 32] = v;
        else              sC[t][j - 48] = v;
    }
    __syncthreads();

    // dt weights for this channel in registers
    float w[DTRV];
    #pragma unroll
    for (int q = 0; q < DTRV / 4; q++) {
        float4 v = *(const float4*)(wdt + (size_t)d * DTRV + q * 4);
        w[4*q] = v.x; w[4*q+1] = v.y; w[4*q+2] = v.z; w[4*q+3] = v.w;
    }
    const float bdtv = bdt[d];

    float rA[NSTATE];
    #pragma unroll
    for (int n = 0; n < NSTATE; n++) rA[n] = -expf(A_log[(size_t)d * NSTATE + n]);
    const float Dv = Dp_[d];
    float h[NSTATE];
    #pragma unroll
    for (int n = 0; n < NSTATE; n++) h[n] = 0.f;

    const size_t rowbase = (size_t)b * SEQ;
    for (int t = 0; t < SEQ; t++) {
        const size_t row = rowbase + t;
        float dot = bdtv;
        #pragma unroll
        for (int j = 0; j < DTRV; j++) dot += sDT[t][j] * w[j];
        float delta = softplusf(dot);
        float u = __bfloat162float(g_ah[row * DINV + d])
                + __bfloat162float(g_al[row * DINV + d]);
        float du = delta * u;
        float y = 0.f;
        #pragma unroll
        for (int n = 0; n < NSTATE; n++) {
            float dA = __expf(delta * rA[n]);
            h[n] = dA * h[n] + du * sB[t][n];
            y += h[n] * sC[t][n];
        }
        float z = g_xz[row * XZW + DINV + d];
        float silu_z = z / (1.0f + __expf(-z));
        float yv = (y + u * Dv) * silu_z;
        __nv_bfloat16 hb = __float2bfloat16_rn(yv);
        g_bh[row * DINV + d] = hb;
        g_bl[row * DINV + d] = __float2bfloat16_rn(yv - __bfloat162float(hb));
    }
}

// ---------------- final LayerNorm stats ---------------------------------------
__global__ void __launch_bounds__(256) ln_stats_kernel()
{
    const int b = blockIdx.x;
    const float4* xp = (const float4*)(g_x + (size_t)b * HEADK);
    float s = 0.f, sq = 0.f;
    for (int i = threadIdx.x; i < HEADK / 4; i += 256) {
        float4 v = xp[i];
        s  += v.x + v.y + v.z + v.w;
        sq += v.x*v.x + v.y*v.y + v.z*v.z + v.w*v.w;
    }
    __shared__ float rs[256], rq[256];
    rs[threadIdx.x] = s; rq[threadIdx.x] = sq; __syncthreads();
    for (int st = 128; st > 0; st >>= 1) {
        if (threadIdx.x < st) { rs[threadIdx.x] += rs[threadIdx.x + st];
                                rq[threadIdx.x] += rq[threadIdx.x + st]; }
        __syncthreads();
    }
    if (threadIdx.x == 0) {
        float mu  = rs[0] / (float)HEADK;
        float var = rq[0] / (float)HEADK - mu * mu;
        g_stats[b] = make_float2(mu, rsqrtf(var + 1e-5f));
    }
}

// ---------------- head: split-K GEMM (LN fused on A load) --------------------
__global__ void __launch_bounds__(256) head_gemm_kernel(
    const float* __restrict__ lng, const float* __restrict__ lnb,
    const float* __restrict__ hw)
{
    constexpr int BK = 16;
    const int slab = blockIdx.x;
    const int kbeg = slab * (HEADK / HSLABS);
    __shared__ float sX[BK][BATCH];
    __shared__ float sW[BK][NCLS];
    const int tid = threadIdx.x;
    const int tx = tid & 15;
    const int ty = tid >> 4;

    float acc[8][2];
    #pragma unroll
    for (int i = 0; i < 8; i++) { acc[i][0] = 0.f; acc[i][1] = 0.f; }

    for (int k0 = kbeg; k0 < kbeg + HEADK / HSLABS; k0 += BK) {
        #pragma unroll
        for (int l = 0; l < 2; l++) {
            int idx = tid + l * 256;
            int row = idx >> 2, kq = (idx & 3) << 2;
            float2 st = g_stats[row];
            float4 v  = *(const float4*)(g_x + (size_t)row * HEADK + k0 + kq);
            float4 gg = *(const float4*)(lng + k0 + kq);
            float4 bb = *(const float4*)(lnb + k0 + kq);
            sX[kq + 0][row] = (v.x - st.x) * st.y * gg.x + bb.x;
            sX[kq + 1][row] = (v.y - st.x) * st.y * gg.y + bb.y;
            sX[kq + 2][row] = (v.z - st.x) * st.y * gg.z + bb.z;
            sX[kq + 3][row] = (v.w - st.x) * st.y * gg.w + bb.w;
        }
        if (tid < 128) {
            int row = tid >> 2, kq = (tid & 3) << 2;
            float4 v = *(const float4*)(hw + (size_t)row * HEADK + k0 + kq);
            sW[kq + 0][row] = v.x; sW[kq + 1][row] = v.y;
            sW[kq + 2][row] = v.z; sW[kq + 3][row] = v.w;
        }
        __syncthreads();
        #pragma unroll
        for (int kk = 0; kk < BK; kk++) {
            float w0 = sW[kk][tx * 2], w1 = sW[kk][tx * 2 + 1];
            #pragma unroll
            for (int i = 0; i < 8; i++) {
                float a = sX[kk][ty * 8 + i];
                acc[i][0] += a * w0;
                acc[i][1] += a * w1;
            }
        }
        __syncthreads();
    }
    #pragma unroll
    for (int i = 0; i < 8; i++) {
        int m = ty * 8 + i;
        g_hpart[((size_t)slab * BATCH + m) * NCLS + tx * 2 + 0] = acc[i][0];
        g_hpart[((size_t)slab * BATCH + m) * NCLS + tx * 2 + 1] = acc[i][1];
    }
}

__global__ void __launch_bounds__(256) head_reduce_kernel(
    const float* __restrict__ head_b, float* __restrict__ out)
{
    int idx = blockIdx.x * blockDim.x + threadIdx.x;
    if (idx < BATCH * NCLS) {
        float s = head_b[idx & (NCLS - 1)];
        for (int sl = 0; sl < HSLABS; sl++)
            s += g_hpart[(size_t)sl * BATCH * NCLS + idx];
        out[idx] = s;
    }
}

// ---------------- host orchestration -----------------------------------------
extern "C" void kernel_launch(void* const* d_in, const int* in_sizes, int n_in,
                              void* d_out, int out_size)
{
    const float* series    = (const float*)d_in[0];
    const float* seg_w     = (const float*)d_in[1];
    const float* seg_b     = (const float*)d_in[2];
    const float* ln_g      = (const float*)d_in[3];
    const float* ln_b      = (const float*)d_in[4];
    const float* in_proj_w = (const float*)d_in[5];
    const float* conv_w    = (const float*)d_in[6];
    const float* conv_b    = (const float*)d_in[7];
    const float* x_proj_w  = (const float*)d_in[8];
    const float* dt_proj_w = (const float*)d_in[9];
    const float* dt_proj_b = (const float*)d_in[10];
    const float* A_log     = (const float*)d_in[11];
    const float* Dw        = (const float*)d_in[12];
    const float* out_proj_w= (const float*)d_in[13];
    const float* hlng      = (const float*)d_in[14];
    const float* hlnb      = (const float*)d_in[15];
    const float* head_w    = (const float*)d_in[16];
    const float* head_b    = (const float*)d_in[17];
    float* out = (float*)d_out;

    float *px, *pxz, *pxdbl;
    __nv_bfloat16 *pah, *pal, *pbh, *pbl, *pwh, *pwl;
    cudaGetSymbolAddress((void**)&px,     g_x);
    cudaGetSymbolAddress((void**)&pxz,    g_xz);
    cudaGetSymbolAddress((void**)&pxdbl,  g_xdbl);
    cudaGetSymbolAddress((void**)&pah,    g_ah);
    cudaGetSymbolAddress((void**)&pal,    g_al);
    cudaGetSymbolAddress((void**)&pbh,    g_bh);
    cudaGetSymbolAddress((void**)&pbl,    g_bl);
    cudaGetSymbolAddress((void**)&pwh,    g_wh);
    cudaGetSymbolAddress((void**)&pwl,    g_wl);

    const int SMEM128 = 2 * (2*128 + 2*128) * 40 * 2;  // 81920
    const int SMEM64  = 2 * (2*64  + 2*64 ) * 40 * 2;  // 40960
    cudaFuncSetAttribute((const void*)hmma_gemm<128,128,2,4,false>,
                         cudaFuncAttributeMaxDynamicSharedMemorySize, SMEM128);
    cudaFuncSetAttribute((const void*)hmma_gemm<128,128,2,4,true>,
                         cudaFuncAttributeMaxDynamicSharedMemorySize, SMEM128);
    cudaFuncSetAttribute((const void*)hmma_gemm<64,64,2,4,false>,
                         cudaFuncAttributeMaxDynamicSharedMemorySize, SMEM64);

    auto split = [](const float* src, __nv_bfloat16* hi, __nv_bfloat16* lo, int n) {
        split_kernel<<<(n/4 + 255)/256, 256>>>(src, hi, lo, n/4);
    };

    // 1) segment linear + LN -> bf16 hi/lo pair A
    seg_ln_kernel<<<dim3(NPATH, BATCH/4), 512>>>(series, seg_w, seg_b, ln_g, ln_b);

    for (int dep = 0; dep < DEPTHN; dep++) {
        // 2) in_proj: [8192,512]x[4096,512]^T -> g_xz (fp32)
        split(in_proj_w + (size_t)dep * XZW * DIMV, pwh, pwl, XZW * DIMV);
        hmma_gemm<128,128,2,4,false><<<dim3(XZW/128, ROWSZ/128), 256, SMEM128>>>(
            pah, pal, pwh, pwl, pxz, nullptr, nullptr,
            ROWSZ, XZW, DIMV, DIMV, DIMV);
        // 3) conv + silu -> pair A (bf16 hi/lo), single-read t-march
        conv_silu_kernel<<<dim3(BATCH, SEQ/16), 256>>>(
            conv_w + (size_t)dep * DINV * 4, conv_b + (size_t)dep * DINV);
        // 4) x_proj: [8192,1024]x[64,1024]^T -> g_xdbl
        split(x_proj_w + (size_t)dep * 64 * DINV, pwh, pwl, 64 * DINV);
        hmma_gemm<64,64,2,4,false><<<dim3(1, ROWSZ/64), 256, SMEM64>>>(
            pah, pal, pwh, pwl, pxdbl, nullptr, nullptr,
            ROWSZ, 64, DINV, DINV, DINV);
        // 5+6) fused dt_proj + softplus + scan + D skip + silu(z) -> pair B
        scan_kernel<<<dim3(BATCH, DINV/256), 256>>>(
            A_log + (size_t)dep * DINV * NSTATE, Dw + (size_t)dep * DINV,
            dt_proj_w + (size_t)dep * DINV * DTRV,
            dt_proj_b + (size_t)dep * DINV);
        // 7) out_proj: [8192,1024]x[512,1024]^T -> g_x fp32 + pair A hi/lo
        split(out_proj_w + (size_t)dep * DIMV * DINV, pwh, pwl, DIMV * DINV);
        hmma_gemm<128,128,2,4,true><<<dim3(DIMV/128, ROWSZ/128), 256, SMEM128>>>(
            pbh, pbl, pwh, pwl, px, pah, pal,
            ROWSZ, DIMV, DINV, DINV, DINV);
    }

    // 8) final LN stats + head GEMM + deterministic reduce
    ln_stats_kernel<<<BATCH, 256>>>();
    head_gemm_kernel<<<HSLABS, 256>>>(hlng, hlnb, head_w);
    head_reduce_kernel<<<(BATCH*NCLS + 255)/256, 256>>>(head_b, out);
}